// round 13
// baseline (speedup 1.0000x reference)
#include <cuda_runtime.h>
#include <math.h>
#include <stdint.h>

// ---------------- problem constants ----------------
#define T_    4
#define B_    32
#define N_    196
#define C_    384
#define H_    8
#define D_    48
#define HID_  1536
#define TB_   128           // T*B
#define NC_   75264         // N*C
#define BNC_  2408448       // B*N*C
#define TBN_  25088         // T*B*N
#define BN_   6272          // B*N
#define MH_   9633792       // BN_*HID_ == TBN_*C_
#define CC_   (C_ * C_)
#define HC_   (HID_ * C_)
#define HH_   (HID_ * HID_)
#define NCAT_ 2688          // 3*C + HID

// ---------------- scratch (device globals; no runtime alloc allowed) ----------------
__device__ float g_bq[MH_];
__device__ float g_bk[MH_];
__device__ float g_bv[MH_];
__device__ float g_ab[MH_];
__device__ float g_af[MH_];
__device__ float g_curr[4 * MH_];
__device__ float g_syn[MH_];
__device__ float g_mem[MH_];
__device__ float g_spk[4 * MH_];
__device__ float g_R[MH_];
__device__ float g_l[MH_];
__device__ float g_ga[MH_];
__device__ float g_gl[MH_];
__device__ float g_o[MH_];
__device__ float g_part[98 * 768];
__device__ float g_stats[768];   // [0:384) mu, [384:768) rstd
// transposed weights for gather-SpMM
__device__ float g_apT[CC_];
__device__ float g_watT[CC_];
__device__ float g_wlsT[CC_];
__device__ float g_fpT[CC_];
__device__ float g_recT[HH_];
__device__ float g_fc2T[HC_];
// concatenated q/k/v/fc1 weights for the merged x-GEMM
__device__ float g_wcat[NCAT_ * C_];
__device__ float g_bcat[NCAT_];

// ---------------- f32x2 packed-FMA helpers ----------------
#define FMA2(D, A, B) \
    asm("fma.rn.f32x2 %0, %1, %2, %0;" : "+l"(D) : "l"(A), "l"(B))
#define PACK2(P, X, Y) \
    asm("mov.b64 %0, {%1, %2};" : "=l"(P) : "f"(X), "f"(Y))
#define UNPACK2(X, Y, P) \
    asm("mov.b64 {%0, %1}, %2;" : "=f"(X), "=f"(Y) : "l"(P))

#define BM 128
#define BN 128
#define BK 16

// ================= SGEMM2 core macro body (BK=16, round-11 proven) =================
// (shared between generic and routed-epilogue variants via inline function)
struct AccP { unsigned long long p[8][4]; };

__device__ __forceinline__ void sgemm_core(
    const float* __restrict__ A, const float* __restrict__ W,
    int K, int bm, int bn, int tid,
    float As[2][BK][BM], float Bs[2][BK][BN], AccP& acc) {
    const int lrow = tid >> 2;
    const int lq = (tid & 3) * 4;
    const float* Ap0 = A + (size_t)(bm + lrow) * K + lq;
    const float* Ap1 = A + (size_t)(bm + lrow + 64) * K + lq;
    const float* Wp0 = W + (size_t)(bn + lrow) * K + lq;
    const float* Wp1 = W + (size_t)(bn + lrow + 64) * K + lq;

    const int tx = tid & 15;
    const int ty = tid >> 4;

#pragma unroll
    for (int i = 0; i < 8; i++)
#pragma unroll
        for (int jp = 0; jp < 4; jp++) acc.p[i][jp] = 0ull;

    float4 a0 = *(const float4*)Ap0;
    float4 a1 = *(const float4*)Ap1;
    float4 w0 = *(const float4*)Wp0;
    float4 w1 = *(const float4*)Wp1;
    As[0][lq + 0][lrow] = a0.x; As[0][lq + 1][lrow] = a0.y;
    As[0][lq + 2][lrow] = a0.z; As[0][lq + 3][lrow] = a0.w;
    As[0][lq + 0][lrow + 64] = a1.x; As[0][lq + 1][lrow + 64] = a1.y;
    As[0][lq + 2][lrow + 64] = a1.z; As[0][lq + 3][lrow + 64] = a1.w;
    Bs[0][lq + 0][lrow] = w0.x; Bs[0][lq + 1][lrow] = w0.y;
    Bs[0][lq + 2][lrow] = w0.z; Bs[0][lq + 3][lrow] = w0.w;
    Bs[0][lq + 0][lrow + 64] = w1.x; Bs[0][lq + 1][lrow + 64] = w1.y;
    Bs[0][lq + 2][lrow + 64] = w1.z; Bs[0][lq + 3][lrow + 64] = w1.w;
    __syncthreads();

    const int nk = K / BK;
    for (int kt = 0; kt < nk; kt++) {
        const int cur = kt & 1;
        if (kt + 1 < nk) {
            const size_t off = (size_t)(kt + 1) * BK;
            a0 = *(const float4*)(Ap0 + off);
            a1 = *(const float4*)(Ap1 + off);
            w0 = *(const float4*)(Wp0 + off);
            w1 = *(const float4*)(Wp1 + off);
        }
#pragma unroll
        for (int kk = 0; kk < BK; kk++) {
            float4 av0 = *(const float4*)&As[cur][kk][ty * 4];
            float4 av1 = *(const float4*)&As[cur][kk][ty * 4 + 64];
            float4 bv0 = *(const float4*)&Bs[cur][kk][tx * 4];
            float4 bv1 = *(const float4*)&Bs[cur][kk][tx * 4 + 64];
            unsigned long long bp[4];
            PACK2(bp[0], bv0.x, bv0.y);
            PACK2(bp[1], bv0.z, bv0.w);
            PACK2(bp[2], bv1.x, bv1.y);
            PACK2(bp[3], bv1.z, bv1.w);
            float avs[8] = {av0.x, av0.y, av0.z, av0.w, av1.x, av1.y, av1.z, av1.w};
#pragma unroll
            for (int i = 0; i < 8; i++) {
                unsigned long long ap;
                PACK2(ap, avs[i], avs[i]);
                FMA2(acc.p[i][0], ap, bp[0]);
                FMA2(acc.p[i][1], ap, bp[1]);
                FMA2(acc.p[i][2], ap, bp[2]);
                FMA2(acc.p[i][3], ap, bp[3]);
            }
        }
        if (kt + 1 < nk) {
            const int nxt = cur ^ 1;
            As[nxt][lq + 0][lrow] = a0.x; As[nxt][lq + 1][lrow] = a0.y;
            As[nxt][lq + 2][lrow] = a0.z; As[nxt][lq + 3][lrow] = a0.w;
            As[nxt][lq + 0][lrow + 64] = a1.x; As[nxt][lq + 1][lrow + 64] = a1.y;
            As[nxt][lq + 2][lrow + 64] = a1.z; As[nxt][lq + 3][lrow + 64] = a1.w;
            Bs[nxt][lq + 0][lrow] = w0.x; Bs[nxt][lq + 1][lrow] = w0.y;
            Bs[nxt][lq + 2][lrow] = w0.z; Bs[nxt][lq + 3][lrow] = w0.w;
            Bs[nxt][lq + 0][lrow + 64] = w1.x; Bs[nxt][lq + 1][lrow + 64] = w1.y;
            Bs[nxt][lq + 2][lrow + 64] = w1.z; Bs[nxt][lq + 3][lrow + 64] = w1.w;
            __syncthreads();
        }
    }
}

// ---- generic GEMM: C[M,N] = A @ W^T + bias ----
__global__ __launch_bounds__(256, 2)
void sgemm_nt(const float* __restrict__ A, const float* __restrict__ W,
              const float* __restrict__ bias, float* __restrict__ C,
              int M, int N, int K) {
    __shared__ float As[2][BK][BM];
    __shared__ float Bs[2][BK][BN];
    const int tid = threadIdx.x;
    const int bm = blockIdx.y * BM;
    const int bn = blockIdx.x * BN;
    const int tx = tid & 15;
    const int ty = tid >> 4;
    AccP acc;
    sgemm_core(A, W, K, bm, bn, tid, As, Bs, acc);

#pragma unroll
    for (int i = 0; i < 8; i++) {
        const int row = bm + ty * 4 + (i & 3) + ((i >> 2) << 6);
#pragma unroll
        for (int jb = 0; jb < 2; jb++) {
            const int col = bn + tx * 4 + jb * 64;
            float4 bv4 = *(const float4*)&bias[col];
            float c0, c1, c2, c3;
            UNPACK2(c0, c1, acc.p[i][jb * 2 + 0]);
            UNPACK2(c2, c3, acc.p[i][jb * 2 + 1]);
            float4 v;
            v.x = c0 + bv4.x;
            v.y = c1 + bv4.y;
            v.z = c2 + bv4.z;
            v.w = c3 + bv4.w;
            *(float4*)&C[(size_t)row * N + col] = v;
        }
    }
}

// ---- merged x-GEMM: W = wcat[2688,384]; routes columns to bq/bk/bv/curr ----
__global__ __launch_bounds__(256, 2)
void sgemm_x4(const float* __restrict__ A, const float* __restrict__ W,
              const float* __restrict__ bias,
              float* __restrict__ bq, float* __restrict__ bk,
              float* __restrict__ bv, float* __restrict__ curr) {
    __shared__ float As[2][BK][BM];
    __shared__ float Bs[2][BK][BN];
    const int tid = threadIdx.x;
    const int bm = blockIdx.y * BM;
    const int bn = blockIdx.x * BN;
    const int tx = tid & 15;
    const int ty = tid >> 4;
    AccP acc;
    sgemm_core(A, W, C_, bm, bn, tid, As, Bs, acc);

    float* Co;
    int cb, ostride;
    if (bn < 1152) {
        Co = (bn < 384) ? bq : ((bn < 768) ? bk : bv);
        cb = bn % 384;
        ostride = C_;
    } else {
        Co = curr;
        cb = bn - 1152;
        ostride = HID_;
    }

#pragma unroll
    for (int i = 0; i < 8; i++) {
        const int row = bm + ty * 4 + (i & 3) + ((i >> 2) << 6);
#pragma unroll
        for (int jb = 0; jb < 2; jb++) {
            const int lcol = tx * 4 + jb * 64;
            float4 bv4 = *(const float4*)&bias[bn + lcol];
            float c0, c1, c2, c3;
            UNPACK2(c0, c1, acc.p[i][jb * 2 + 0]);
            UNPACK2(c2, c3, acc.p[i][jb * 2 + 1]);
            float4 v;
            v.x = c0 + bv4.x;
            v.y = c1 + bv4.y;
            v.z = c2 + bv4.z;
            v.w = c3 + bv4.w;
            *(float4*)&Co[(size_t)row * ostride + cb + lcol] = v;
        }
    }
}

// ---------------- concat q/k/v/fc1 weights + biases ----------------
__global__ void concat_w(const float* __restrict__ q_w, const float* __restrict__ k_w,
                         const float* __restrict__ v_w, const float* __restrict__ fc1_w,
                         const float* __restrict__ q_b, const float* __restrict__ k_b,
                         const float* __restrict__ v_b, const float* __restrict__ fc1_b,
                         float* __restrict__ wcat, float* __restrict__ bcat) {
    const int j = blockIdx.x;
    const int tid = threadIdx.x;
    const float* src;
    const float* bsrc;
    int r;
    if (j < 384)       { src = q_w;   bsrc = q_b;   r = j; }
    else if (j < 768)  { src = k_w;   bsrc = k_b;   r = j - 384; }
    else if (j < 1152) { src = v_w;   bsrc = v_b;   r = j - 768; }
    else               { src = fc1_w; bsrc = fc1_b; r = j - 1152; }
    wcat[(size_t)j * C_ + tid] = src[(size_t)r * C_ + tid];
    if (tid == 0) bcat[j] = bsrc[r];
}

// ================= gather-SpMM (binary) =================
template<int NV>
__global__ __launch_bounds__(256)
void spmm_gather(const float* __restrict__ A, const float* __restrict__ WT,
                 const float* __restrict__ bias, float* __restrict__ C,
                 int N, int K) {
    __shared__ short idxs[1536];
    __shared__ int wcnt[8];
    __shared__ int woff[8];
    __shared__ int s_nact;

    const int m = blockIdx.x;
    const int tid = threadIdx.x;
    const int lane = tid & 31;
    const int wid = tid >> 5;
    const float* arow = A + (size_t)m * K;
    const int nch = K >> 5;

    int cnt = 0;
    for (int c = wid; c < nch; c += 8) {
        unsigned mask = __ballot_sync(0xffffffffu, arow[c * 32 + lane] != 0.0f);
        cnt += __popc(mask);
    }
    if (lane == 0) wcnt[wid] = cnt;
    __syncthreads();
    if (tid == 0) {
        int tot = 0;
#pragma unroll
        for (int w = 0; w < 8; w++) { woff[w] = tot; tot += wcnt[w]; }
        s_nact = tot;
    }
    __syncthreads();

    int base = woff[wid];
    for (int c = wid; c < nch; c += 8) {
        int k = c * 32 + lane;
        bool act = (arow[k] != 0.0f);
        unsigned mask = __ballot_sync(0xffffffffu, act);
        if (act) idxs[base + __popc(mask & ((1u << lane) - 1u))] = (short)k;
        base += __popc(mask);
    }
    __syncthreads();

    const int nact = s_nact;
    float acc[NV];
#pragma unroll
    for (int v = 0; v < NV; v++) {
        int n = tid + v * 256;
        acc[v] = (n < N) ? bias[n] : 0.0f;
    }

    int i = 0;
    for (; i + 2 <= nact; i += 2) {
        const float* w0 = WT + (size_t)idxs[i] * N;
        const float* w1 = WT + (size_t)idxs[i + 1] * N;
        float r0[NV], r1[NV];
#pragma unroll
        for (int v = 0; v < NV; v++) {
            int n = tid + v * 256;
            if (n < N) { r0[v] = w0[n]; r1[v] = w1[n]; }
        }
#pragma unroll
        for (int v = 0; v < NV; v++) {
            int n = tid + v * 256;
            if (n < N) { acc[v] += r0[v]; acc[v] += r1[v]; }
        }
    }
    if (i < nact) {
        const float* w0 = WT + (size_t)idxs[i] * N;
#pragma unroll
        for (int v = 0; v < NV; v++) {
            int n = tid + v * 256;
            if (n < N) acc[v] += w0[n];
        }
    }

#pragma unroll
    for (int v = 0; v < NV; v++) {
        int n = tid + v * 256;
        if (n < N) C[(size_t)m * N + n] = acc[v];
    }
}

// ======= fused ARIG fuse + fp gather: o[m,:] = fp_b + sum_k fu[m,k]*fpT[k,:] =======
// fu computed on the fly: fu = af*sigmoid(gl) + lf*sigmoid(ga); active iff af|lf spike.
template<int NV>
__global__ __launch_bounds__(256)
void spmm_gather_fuse(const float* __restrict__ af, const float* __restrict__ lf,
                      const float* __restrict__ ga, const float* __restrict__ gl,
                      const float* __restrict__ WT, const float* __restrict__ bias,
                      float* __restrict__ C, int N, int K) {
    __shared__ short idxs[384];
    __shared__ float vals[384];
    __shared__ int wcnt[8];
    __shared__ int woff[8];
    __shared__ int s_nact;

    const int m = blockIdx.x;
    const int tid = threadIdx.x;
    const int lane = tid & 31;
    const int wid = tid >> 5;
    const float* arow = af + (size_t)m * K;
    const float* lrow = lf + (size_t)m * K;
    const float* garow = ga + (size_t)m * K;
    const float* glrow = gl + (size_t)m * K;
    const int nch = K >> 5;

    int cnt = 0;
    for (int c = wid; c < nch; c += 8) {
        int k = c * 32 + lane;
        bool act = (arow[k] != 0.0f) || (lrow[k] != 0.0f);
        unsigned mask = __ballot_sync(0xffffffffu, act);
        cnt += __popc(mask);
    }
    if (lane == 0) wcnt[wid] = cnt;
    __syncthreads();
    if (tid == 0) {
        int tot = 0;
#pragma unroll
        for (int w = 0; w < 8; w++) { woff[w] = tot; tot += wcnt[w]; }
        s_nact = tot;
    }
    __syncthreads();

    int base = woff[wid];
    for (int c = wid; c < nch; c += 8) {
        int k = c * 32 + lane;
        float a = arow[k];
        float l = lrow[k];
        bool act = (a != 0.0f) || (l != 0.0f);
        unsigned mask = __ballot_sync(0xffffffffu, act);
        if (act) {
            float gate_attn = 1.0f / (1.0f + expf(-glrow[k]));
            float gate_lsm  = 1.0f / (1.0f + expf(-garow[k]));
            float fu = a * gate_attn + l * gate_lsm;
            int p = base + __popc(mask & ((1u << lane) - 1u));
            idxs[p] = (short)k;
            vals[p] = fu;
        }
        base += __popc(mask);
    }
    __syncthreads();

    const int nact = s_nact;
    float acc[NV];
#pragma unroll
    for (int v = 0; v < NV; v++) {
        int n = tid + v * 256;
        acc[v] = (n < N) ? bias[n] : 0.0f;
    }

    for (int i = 0; i < nact; i++) {
        const float* w0 = WT + (size_t)idxs[i] * N;
        const float a = vals[i];
#pragma unroll
        for (int v = 0; v < NV; v++) {
            int n = tid + v * 256;
            if (n < N) acc[v] = fmaf(a, w0[n], acc[v]);
        }
    }

#pragma unroll
    for (int v = 0; v < NV; v++) {
        int n = tid + v * 256;
        if (n < N) C[(size_t)m * N + n] = acc[v];
    }
}

// ---------------- transpose W[Nw,Kw] -> WT[Kw,Nw] ----------------
__global__ void transpose_k(const float* __restrict__ W, float* __restrict__ WT,
                            int Nw, int Kw) {
    __shared__ float t[32][33];
    int bx = blockIdx.x * 32, by = blockIdx.y * 32;
    int x = bx + threadIdx.x;
#pragma unroll
    for (int j = 0; j < 32; j += 8) {
        int y = by + threadIdx.y + j;
        if (y < Nw && x < Kw) t[threadIdx.y + j][threadIdx.x] = W[(size_t)y * Kw + x];
    }
    __syncthreads();
    int x2 = by + threadIdx.x;
#pragma unroll
    for (int j = 0; j < 32; j += 8) {
        int y2 = bx + threadIdx.y + j;
        if (y2 < Kw && x2 < Nw) WT[(size_t)y2 * Nw + x2] = t[threadIdx.x][threadIdx.y + j];
    }
}

// ---------------- LIF scan (in-place), depth-4 prefetch ----------------
__global__ void lif_seq(float* __restrict__ buf, int steps, long stride, long nelem,
                        const float* __restrict__ lif_w, int widx) {
    long idx = (long)blockIdx.x * blockDim.x + threadIdx.x;
    if (idx >= nelem) return;
    const float decay = 1.0f / (1.0f + expf(-lif_w[widx]));
    float v = 0.0f;
    float xs[4];
#pragma unroll
    for (int t = 0; t < 4; t++)
        if (t < steps) xs[t] = buf[(long)t * stride + idx];
    for (int t = 0; t < steps; t++) {
        float x = xs[t & 3];
        if (t + 4 < steps) xs[t & 3] = buf[(long)(t + 4) * stride + idx];
        v = v + (x - v) * decay;
        float s = (v >= 1.0f) ? 1.0f : 0.0f;
        buf[(long)t * stride + idx] = s;
        v *= (1.0f - s);
    }
}

// ---------------- merged q/k/v LIF ----------------
__global__ void lif_seq3(float* __restrict__ b0, float* __restrict__ b1,
                         float* __restrict__ b2, const float* __restrict__ lif_w) {
    long idx = (long)blockIdx.x * blockDim.x + threadIdx.x;
    if (idx >= (long)NC_) return;
    const int which = blockIdx.y;
    float* buf = (which == 0) ? b0 : ((which == 1) ? b1 : b2);
    const float decay = 1.0f / (1.0f + expf(-lif_w[which]));
    float v = 0.0f;
    float xs[4];
#pragma unroll
    for (int t = 0; t < 4; t++) xs[t] = buf[(long)t * NC_ + idx];
    for (int t = 0; t < TB_; t++) {
        float x = xs[t & 3];
        if (t + 4 < TB_) xs[t & 3] = buf[(long)(t + 4) * NC_ + idx];
        v = v + (x - v) * decay;
        float s = (v >= 1.0f) ? 1.0f : 0.0f;
        buf[(long)t * NC_ + idx] = s;
        v *= (1.0f - s);
    }
}

// ---------------- spiking attention with v-sparsity fast path ----------------
__global__ __launch_bounds__(256)
void attn_kernel(const float* __restrict__ sq, const float* __restrict__ sk,
                 const float* __restrict__ sv, float* __restrict__ abuf) {
    const int tb = blockIdx.x >> 3;
    const int h = blockIdx.x & 7;
    __shared__ unsigned long long qb[N_], kb[N_], vb[N_];
    __shared__ unsigned char cnt[N_ * 200];
    __shared__ int pairs[768];
    __shared__ int s_np;
    const int tid = threadIdx.x;

    for (int i = tid; i < N_; i += 256) { qb[i] = 0ull; kb[i] = 0ull; vb[i] = 0ull; }
    __syncthreads();

    const long base = (long)tb * NC_ + h * D_;
    for (int e = tid; e < N_ * D_; e += 256) {
        int n = e / D_, d = e % D_;
        long off = base + (long)n * C_ + d;
        unsigned long long bit = 1ull << d;
        if (sq[off] != 0.0f) atomicOr(&qb[n], bit);
        if (sk[off] != 0.0f) atomicOr(&kb[n], bit);
        if (sv[off] != 0.0f) atomicOr(&vb[n], bit);
    }
    __syncthreads();

    if (tid == 0) {
        int np = 0;
        for (int m = 0; m < N_; m++) {
            unsigned long long w = vb[m];
            while (w) {
                int d = __ffsll((long long)w) - 1;
                if (np < 768) pairs[np] = (m << 6) | d;
                np++;
                w &= w - 1;
            }
        }
        s_np = np;
    }
    __syncthreads();

    const float scale = 0.14433756729740643f;  // 48^-0.5
    const int np = s_np;
    const long obase = (long)tb * NC_ + h * (D_ * N_);

    if (np <= 768) {
        for (int o = tid; o < N_ * D_; o += 256) {
            int n = o / D_, d = o - n * D_;
            int acc = 0;
            for (int p = 0; p < np; p++) {
                int pm = pairs[p];
                if ((pm & 63) == d) acc += __popcll(qb[n] & kb[pm >> 6]);
            }
            abuf[obase + d * N_ + n] = scale * (float)acc;
        }
        return;
    }

    for (int i = tid; i < N_ * N_; i += 256) {
        int n = i / N_, m = i - n * N_;
        cnt[n * 200 + m] = (unsigned char)__popcll(qb[n] & kb[m]);
    }
    __syncthreads();

    for (int o = tid; o < N_ * D_; o += 256) {
        int n = o / D_, d = o - n * D_;
        const unsigned char* crow = &cnt[n * 200];
        int acc = 0;
#pragma unroll 4
        for (int m = 0; m < N_; m++)
            acc += (int)crow[m] * (int)((vb[m] >> d) & 1ull);
        abuf[obase + d * N_ + n] = scale * (float)acc;
    }
}

// ---------------- LSM (RSynaptic) elementwise steps ----------------
__global__ void lsm_step0(const float* __restrict__ curr, const float* __restrict__ rec_b,
                          float* __restrict__ syn, float* __restrict__ mem,
                          float* __restrict__ spk) {
    long idx = (long)blockIdx.x * blockDim.x + threadIdx.x;
    if (idx >= (long)MH_) return;
    int hc = (int)(idx % HID_);
    float s = curr[idx] + rec_b[hc];
    syn[idx] = s;
    mem[idx] = s;
    spk[idx] = (s - 1.0f >= 0.0f) ? 1.0f : 0.0f;
}

__global__ void lsm_step(const float* __restrict__ curr_t, const float* __restrict__ R,
                         float* __restrict__ syn, float* __restrict__ mem,
                         const float* __restrict__ spk_prev, float* __restrict__ spk_out) {
    long idx = (long)blockIdx.x * blockDim.x + threadIdx.x;
    if (idx >= (long)MH_) return;
    float sp = spk_prev[idx];
    float s = 0.9f * syn[idx] + curr_t[idx] + R[idx];
    float m = 0.8f * mem[idx] + s - sp * 1.0f;
    syn[idx] = s;
    mem[idx] = m;
    spk_out[idx] = (m - 1.0f >= 0.0f) ? 1.0f : 0.0f;
}

// ---------------- BatchNorm stats (deterministic 2-stage) ----------------
__global__ void bn_partial(const float* __restrict__ X, float* __restrict__ part) {
    int c = threadIdx.x;
    long r0 = (long)blockIdx.x * 256;
    float s = 0.0f, s2 = 0.0f;
    for (int r = 0; r < 256; r++) {
        float v = X[(r0 + r) * C_ + c];
        s += v;
        s2 += v * v;
    }
    part[blockIdx.x * 768 + c] = s;
    part[blockIdx.x * 768 + 384 + c] = s2;
}

__global__ void bn_finalize(const float* __restrict__ part, float* __restrict__ stats) {
    int c = threadIdx.x;
    float s = 0.0f, s2 = 0.0f;
    for (int p = 0; p < 98; p++) {
        s += part[p * 768 + c];
        s2 += part[p * 768 + 384 + c];
    }
    const float inv = 1.0f / 25088.0f;
    float m = s * inv;
    float var = s2 * inv - m * m;
    stats[c] = m;
    stats[384 + c] = 1.0f / sqrtf(var + 1e-5f);
}

// ---------------- fused BN-apply + 4-step LIF (+ optional residual) ----------------
__global__ void bn_lif4(const float* __restrict__ lin, float* __restrict__ out,
                        const float* __restrict__ stats,
                        const float* __restrict__ gamma, const float* __restrict__ beta,
                        const float* __restrict__ lif_w, int widx,
                        const float* __restrict__ xadd) {
    long idx = (long)blockIdx.x * blockDim.x + threadIdx.x;
    if (idx >= (long)BNC_) return;
    int c = (int)(idx % C_);
    float mu = stats[c], rstd = stats[384 + c];
    float gg = gamma[c], bb = beta[c];
    float decay = 1.0f / (1.0f + expf(-lif_w[widx]));
    float v = 0.0f;
    float xs[4];
#pragma unroll
    for (int t = 0; t < 4; t++) xs[t] = lin[(long)t * BNC_ + idx];
#pragma unroll
    for (int t = 0; t < 4; t++) {
        long o = (long)t * BNC_ + idx;
        float xv = (xs[t] - mu) * rstd * gg + bb;
        v = v + (xv - v) * decay;
        float s = (v >= 1.0f) ? 1.0f : 0.0f;
        v *= (1.0f - s);
        if (xadd) out[o] = xadd[o] + s;
        else      out[o] = s;
    }
}

// ---------------- launch ----------------
extern "C" void kernel_launch(void* const* d_in, const int* in_sizes, int n_in,
                              void* d_out, int out_size) {
    const float* x      = (const float*)d_in[0];
    const float* q_w    = (const float*)d_in[1];
    const float* q_b    = (const float*)d_in[2];
    const float* k_w    = (const float*)d_in[3];
    const float* k_b    = (const float*)d_in[4];
    const float* v_w    = (const float*)d_in[5];
    const float* v_b    = (const float*)d_in[6];
    const float* ap_w   = (const float*)d_in[7];
    const float* ap_b   = (const float*)d_in[8];
    const float* fc1_w  = (const float*)d_in[9];
    const float* fc1_b  = (const float*)d_in[10];
    const float* rec_w  = (const float*)d_in[11];
    const float* rec_b  = (const float*)d_in[12];
    const float* fc2_w  = (const float*)d_in[13];
    const float* fc2_b  = (const float*)d_in[14];
    const float* bnl_g  = (const float*)d_in[15];
    const float* bnl_b  = (const float*)d_in[16];
    const float* watt_w = (const float*)d_in[17];
    const float* watt_b = (const float*)d_in[18];
    const float* wlsm_w = (const float*)d_in[19];
    const float* wlsm_b = (const float*)d_in[20];
    const float* fp_w   = (const float*)d_in[21];
    const float* fp_b   = (const float*)d_in[22];
    const float* bnf_g  = (const float*)d_in[23];
    const float* bnf_b  = (const float*)d_in[24];
    const float* lif_w  = (const float*)d_in[25];
    float* out = (float*)d_out;

    float *bq, *bk, *bv, *ab, *af, *curr, *syn, *mem, *spk, *R, *l, *ga, *gl, *o, *part, *stats;
    float *apT, *watT, *wlsT, *fpT, *recT, *fc2T, *wcat, *bcat;
    cudaGetSymbolAddress((void**)&bq, g_bq);
    cudaGetSymbolAddress((void**)&bk, g_bk);
    cudaGetSymbolAddress((void**)&bv, g_bv);
    cudaGetSymbolAddress((void**)&ab, g_ab);
    cudaGetSymbolAddress((void**)&af, g_af);
    cudaGetSymbolAddress((void**)&curr, g_curr);
    cudaGetSymbolAddress((void**)&syn, g_syn);
    cudaGetSymbolAddress((void**)&mem, g_mem);
    cudaGetSymbolAddress((void**)&spk, g_spk);
    cudaGetSymbolAddress((void**)&R, g_R);
    cudaGetSymbolAddress((void**)&l, g_l);
    cudaGetSymbolAddress((void**)&ga, g_ga);
    cudaGetSymbolAddress((void**)&gl, g_gl);
    cudaGetSymbolAddress((void**)&o, g_o);
    cudaGetSymbolAddress((void**)&part, g_part);
    cudaGetSymbolAddress((void**)&stats, g_stats);
    cudaGetSymbolAddress((void**)&apT, g_apT);
    cudaGetSymbolAddress((void**)&watT, g_watT);
    cudaGetSymbolAddress((void**)&wlsT, g_wlsT);
    cudaGetSymbolAddress((void**)&fpT, g_fpT);
    cudaGetSymbolAddress((void**)&recT, g_recT);
    cudaGetSymbolAddress((void**)&fc2T, g_fc2T);
    cudaGetSymbolAddress((void**)&wcat, g_wcat);
    cudaGetSymbolAddress((void**)&bcat, g_bcat);

    const dim3 gX(NCAT_ / BN, TBN_ / BM);  // (21, 196) merged qkv+fc1
    const dim3 gR(HID_ / BN, BN_ / BM);    // (12, 49)  rec dense
    const int nb75k = (NC_ + 255) / 256;
    const int nbBNC = (BNC_ + 255) / 256;
    const int nbMH  = (MH_ + 255) / 256;
    const dim3 tb32(32, 8);
    const dim3 gT384(C_ / 32, C_ / 32);
    const dim3 gT1536(HID_ / 32, HID_ / 32);
    const dim3 gTfc2(HID_ / 32, C_ / 32);

    // ---- prep: weight transposes + concat ----
    transpose_k<<<gT384, tb32>>>(ap_w, apT, C_, C_);
    transpose_k<<<gT384, tb32>>>(watt_w, watT, C_, C_);
    transpose_k<<<gT384, tb32>>>(wlsm_w, wlsT, C_, C_);
    transpose_k<<<gT384, tb32>>>(fp_w, fpT, C_, C_);
    transpose_k<<<gT1536, tb32>>>(rec_w, recT, HID_, HID_);
    transpose_k<<<gTfc2, tb32>>>(fc2_w, fc2T, C_, HID_);
    concat_w<<<NCAT_, 384>>>(q_w, k_w, v_w, fc1_w, q_b, k_b, v_b, fc1_b, wcat, bcat);

    // --- merged x-GEMM: q/k/v/fc1 in one launch ---
    sgemm_x4<<<gX, 256>>>(x, wcat, bcat, bq, bk, bv, curr);

    // --- SSA branch ---
    lif_seq3<<<dim3(nb75k, 3), 256>>>(bq, bk, bv, lif_w);
    attn_kernel<<<TB_ * H_, 256>>>(bq, bk, bv, ab);
    lif_seq<<<nbBNC, 256>>>(ab, T_, BNC_, BNC_, lif_w, 3);
    spmm_gather<2><<<TBN_, 256>>>(ab, apT, ap_b, af, C_, C_);
    lif_seq<<<nb75k, 256>>>(af, TB_, NC_, NC_, lif_w, 4);

    // --- LSM branch ---
    lsm_step0<<<nbMH, 256>>>(curr, rec_b, syn, mem, spk);
    spmm_gather<6><<<BN_, 256>>>(spk, recT, rec_b, R, HID_, HID_);
    lsm_step<<<nbMH, 256>>>(curr + (size_t)MH_, R, syn, mem, spk, spk + (size_t)MH_);
    spmm_gather<6><<<BN_, 256>>>(spk + (size_t)MH_, recT, rec_b, R, HID_, HID_);
    lsm_step<<<nbMH, 256>>>(curr + 2 * (size_t)MH_, R, syn, mem,
                            spk + (size_t)MH_, spk + 2 * (size_t)MH_);
    sgemm_nt<<<gR, 256>>>(spk + 2 * (size_t)MH_, rec_w, rec_b, R, BN_, HID_, HID_);
    lsm_step<<<nbMH, 256>>>(curr + 3 * (size_t)MH_, R, syn, mem,
                            spk + 2 * (size_t)MH_, spk + 3 * (size_t)MH_);

    // fc2 split by t: t0/t1 gather, t2+t3 dense
    spmm_gather<2><<<BN_, 256>>>(spk, fc2T, fc2_b, l, C_, HID_);
    spmm_gather<2><<<BN_, 256>>>(spk + (size_t)MH_, fc2T, fc2_b,
                                 l + (size_t)BN_ * C_, C_, HID_);
    sgemm_nt<<<dim3(C_ / BN, (2 * BN_) / BM), 256>>>(spk + 2 * (size_t)MH_, fc2_w, fc2_b,
                                                     l + 2 * (size_t)BN_ * C_,
                                                     2 * BN_, C_, HID_);
    bn_partial<<<98, 384>>>(l, part);
    bn_finalize<<<1, 384>>>(part, stats);
    bn_lif4<<<nbBNC, 256>>>(l, l, stats, bnl_g, bnl_b, lif_w, 5, nullptr);

    // --- ARIG fusion ---
    spmm_gather<2><<<TBN_, 256>>>(af, watT, watt_b, ga, C_, C_);
    spmm_gather<2><<<TBN_, 256>>>(l, wlsT, wlsm_b, gl, C_, C_);
    spmm_gather_fuse<2><<<TBN_, 256>>>(af, l, ga, gl, fpT, fp_b, o, C_, C_);
    bn_partial<<<98, 384>>>(o, part);
    bn_finalize<<<1, 384>>>(part, stats);
    bn_lif4<<<nbBNC, 256>>>(o, out, stats, bnf_g, bnf_b, lif_w, 6, x);
}

// round 14
// speedup vs baseline: 1.0238x; 1.0238x over previous
#include <cuda_runtime.h>
#include <math.h>
#include <stdint.h>

// ---------------- problem constants ----------------
#define T_    4
#define B_    32
#define N_    196
#define C_    384
#define H_    8
#define D_    48
#define HID_  1536
#define TB_   128           // T*B
#define NC_   75264         // N*C
#define BNC_  2408448       // B*N*C
#define TBN_  25088         // T*B*N
#define BN_   6272          // B*N
#define MH_   9633792       // BN_*HID_ == TBN_*C_
#define CC_   (C_ * C_)
#define HC_   (HID_ * C_)
#define HH_   (HID_ * HID_)

// ---------------- scratch (device globals; no runtime alloc allowed) ----------------
__device__ float g_bq[MH_];
__device__ float g_bk[MH_];
__device__ float g_bv[MH_];
__device__ float g_ab[MH_];
__device__ float g_af[MH_];
__device__ float g_curr[4 * MH_];
__device__ float g_syn[MH_];
__device__ float g_mem[MH_];
__device__ float g_spk[4 * MH_];
__device__ float g_l[MH_];
__device__ float g_ga[MH_];
__device__ float g_gl[MH_];
__device__ float g_o[MH_];
__device__ float g_part[98 * 768];
__device__ float g_stats[768];   // [0:384) mu, [384:768) rstd
// transposed weights for gather-SpMM
__device__ float g_apT[CC_];
__device__ float g_watT[CC_];
__device__ float g_wlsT[CC_];
__device__ float g_fpT[CC_];
__device__ float g_recT[HH_];
__device__ float g_fc2T[HC_];

// ---------------- f32x2 packed-FMA helpers ----------------
#define FMA2(D, A, B) \
    asm("fma.rn.f32x2 %0, %1, %2, %0;" : "+l"(D) : "l"(A), "l"(B))
#define PACK2(P, X, Y) \
    asm("mov.b64 %0, {%1, %2};" : "=l"(P) : "f"(X), "f"(Y))
#define UNPACK2(X, Y, P) \
    asm("mov.b64 {%0, %1}, %2;" : "=f"(X), "=f"(Y) : "l"(P))

#define BM 128
#define BN 128
#define BK 16

// ================= SGEMM2 core (BK=16, round-11 proven) =================
struct AccP { unsigned long long p[8][4]; };

__device__ __forceinline__ void sgemm_core(
    const float* __restrict__ A, const float* __restrict__ W,
    int K, int bm, int bn, int tid,
    float As[2][BK][BM], float Bs[2][BK][BN], AccP& acc) {
    const int lrow = tid >> 2;
    const int lq = (tid & 3) * 4;
    const float* Ap0 = A + (size_t)(bm + lrow) * K + lq;
    const float* Ap1 = A + (size_t)(bm + lrow + 64) * K + lq;
    const float* Wp0 = W + (size_t)(bn + lrow) * K + lq;
    const float* Wp1 = W + (size_t)(bn + lrow + 64) * K + lq;

    const int tx = tid & 15;
    const int ty = tid >> 4;

#pragma unroll
    for (int i = 0; i < 8; i++)
#pragma unroll
        for (int jp = 0; jp < 4; jp++) acc.p[i][jp] = 0ull;

    float4 a0 = *(const float4*)Ap0;
    float4 a1 = *(const float4*)Ap1;
    float4 w0 = *(const float4*)Wp0;
    float4 w1 = *(const float4*)Wp1;
    As[0][lq + 0][lrow] = a0.x; As[0][lq + 1][lrow] = a0.y;
    As[0][lq + 2][lrow] = a0.z; As[0][lq + 3][lrow] = a0.w;
    As[0][lq + 0][lrow + 64] = a1.x; As[0][lq + 1][lrow + 64] = a1.y;
    As[0][lq + 2][lrow + 64] = a1.z; As[0][lq + 3][lrow + 64] = a1.w;
    Bs[0][lq + 0][lrow] = w0.x; Bs[0][lq + 1][lrow] = w0.y;
    Bs[0][lq + 2][lrow] = w0.z; Bs[0][lq + 3][lrow] = w0.w;
    Bs[0][lq + 0][lrow + 64] = w1.x; Bs[0][lq + 1][lrow + 64] = w1.y;
    Bs[0][lq + 2][lrow + 64] = w1.z; Bs[0][lq + 3][lrow + 64] = w1.w;
    __syncthreads();

    const int nk = K / BK;
    for (int kt = 0; kt < nk; kt++) {
        const int cur = kt & 1;
        if (kt + 1 < nk) {
            const size_t off = (size_t)(kt + 1) * BK;
            a0 = *(const float4*)(Ap0 + off);
            a1 = *(const float4*)(Ap1 + off);
            w0 = *(const float4*)(Wp0 + off);
            w1 = *(const float4*)(Wp1 + off);
        }
#pragma unroll
        for (int kk = 0; kk < BK; kk++) {
            float4 av0 = *(const float4*)&As[cur][kk][ty * 4];
            float4 av1 = *(const float4*)&As[cur][kk][ty * 4 + 64];
            float4 bv0 = *(const float4*)&Bs[cur][kk][tx * 4];
            float4 bv1 = *(const float4*)&Bs[cur][kk][tx * 4 + 64];
            unsigned long long bp[4];
            PACK2(bp[0], bv0.x, bv0.y);
            PACK2(bp[1], bv0.z, bv0.w);
            PACK2(bp[2], bv1.x, bv1.y);
            PACK2(bp[3], bv1.z, bv1.w);
            float avs[8] = {av0.x, av0.y, av0.z, av0.w, av1.x, av1.y, av1.z, av1.w};
#pragma unroll
            for (int i = 0; i < 8; i++) {
                unsigned long long ap;
                PACK2(ap, avs[i], avs[i]);
                FMA2(acc.p[i][0], ap, bp[0]);
                FMA2(acc.p[i][1], ap, bp[1]);
                FMA2(acc.p[i][2], ap, bp[2]);
                FMA2(acc.p[i][3], ap, bp[3]);
            }
        }
        if (kt + 1 < nk) {
            const int nxt = cur ^ 1;
            As[nxt][lq + 0][lrow] = a0.x; As[nxt][lq + 1][lrow] = a0.y;
            As[nxt][lq + 2][lrow] = a0.z; As[nxt][lq + 3][lrow] = a0.w;
            As[nxt][lq + 0][lrow + 64] = a1.x; As[nxt][lq + 1][lrow + 64] = a1.y;
            As[nxt][lq + 2][lrow + 64] = a1.z; As[nxt][lq + 3][lrow + 64] = a1.w;
            Bs[nxt][lq + 0][lrow] = w0.x; Bs[nxt][lq + 1][lrow] = w0.y;
            Bs[nxt][lq + 2][lrow] = w0.z; Bs[nxt][lq + 3][lrow] = w0.w;
            Bs[nxt][lq + 0][lrow + 64] = w1.x; Bs[nxt][lq + 1][lrow + 64] = w1.y;
            Bs[nxt][lq + 2][lrow + 64] = w1.z; Bs[nxt][lq + 3][lrow + 64] = w1.w;
            __syncthreads();
        }
    }
}

// ---- generic GEMM: C[M,N] = A @ W^T + bias ----
__global__ __launch_bounds__(256, 2)
void sgemm_nt(const float* __restrict__ A, const float* __restrict__ W,
              const float* __restrict__ bias, float* __restrict__ C,
              int M, int N, int K) {
    __shared__ float As[2][BK][BM];
    __shared__ float Bs[2][BK][BN];
    const int tid = threadIdx.x;
    const int bm = blockIdx.y * BM;
    const int bn = blockIdx.x * BN;
    const int tx = tid & 15;
    const int ty = tid >> 4;
    AccP acc;
    sgemm_core(A, W, K, bm, bn, tid, As, Bs, acc);

#pragma unroll
    for (int i = 0; i < 8; i++) {
        const int row = bm + ty * 4 + (i & 3) + ((i >> 2) << 6);
#pragma unroll
        for (int jb = 0; jb < 2; jb++) {
            const int col = bn + tx * 4 + jb * 64;
            float4 bv4 = *(const float4*)&bias[col];
            float c0, c1, c2, c3;
            UNPACK2(c0, c1, acc.p[i][jb * 2 + 0]);
            UNPACK2(c2, c3, acc.p[i][jb * 2 + 1]);
            float4 v;
            v.x = c0 + bv4.x;
            v.y = c1 + bv4.y;
            v.z = c2 + bv4.z;
            v.w = c3 + bv4.w;
            *(float4*)&C[(size_t)row * N + col] = v;
        }
    }
}

// ---- dense rec GEMM with fused LSM update (t=3 step); N = HID_ ----
__global__ __launch_bounds__(256, 2)
void sgemm_nt_lsm(const float* __restrict__ A, const float* __restrict__ W,
                  const float* __restrict__ bias,
                  const float* __restrict__ curr_t, float* __restrict__ syn,
                  float* __restrict__ mem, const float* __restrict__ spk_prev,
                  float* __restrict__ spk_out, int M, int K) {
    __shared__ float As[2][BK][BM];
    __shared__ float Bs[2][BK][BN];
    const int tid = threadIdx.x;
    const int bm = blockIdx.y * BM;
    const int bn = blockIdx.x * BN;
    const int tx = tid & 15;
    const int ty = tid >> 4;
    AccP acc;
    sgemm_core(A, W, K, bm, bn, tid, As, Bs, acc);

#pragma unroll
    for (int i = 0; i < 8; i++) {
        const int row = bm + ty * 4 + (i & 3) + ((i >> 2) << 6);
#pragma unroll
        for (int jb = 0; jb < 2; jb++) {
            const int col = bn + tx * 4 + jb * 64;
            const size_t idx = (size_t)row * HID_ + col;
            float4 bv4 = *(const float4*)&bias[col];
            float c0, c1, c2, c3;
            UNPACK2(c0, c1, acc.p[i][jb * 2 + 0]);
            UNPACK2(c2, c3, acc.p[i][jb * 2 + 1]);
            float Rv[4] = {c0 + bv4.x, c1 + bv4.y, c2 + bv4.z, c3 + bv4.w};
            float4 sy = *(const float4*)&syn[idx];
            float4 me = *(const float4*)&mem[idx];
            float4 cu = *(const float4*)&curr_t[idx];
            float4 sp = *(const float4*)&spk_prev[idx];
            float4 syo, meo, spo;
            float s, mm;
            s = 0.9f * sy.x + cu.x + Rv[0]; mm = 0.8f * me.x + s - sp.x;
            syo.x = s; meo.x = mm; spo.x = (mm - 1.0f >= 0.0f) ? 1.0f : 0.0f;
            s = 0.9f * sy.y + cu.y + Rv[1]; mm = 0.8f * me.y + s - sp.y;
            syo.y = s; meo.y = mm; spo.y = (mm - 1.0f >= 0.0f) ? 1.0f : 0.0f;
            s = 0.9f * sy.z + cu.z + Rv[2]; mm = 0.8f * me.z + s - sp.z;
            syo.z = s; meo.z = mm; spo.z = (mm - 1.0f >= 0.0f) ? 1.0f : 0.0f;
            s = 0.9f * sy.w + cu.w + Rv[3]; mm = 0.8f * me.w + s - sp.w;
            syo.w = s; meo.w = mm; spo.w = (mm - 1.0f >= 0.0f) ? 1.0f : 0.0f;
            *(float4*)&syn[idx] = syo;
            *(float4*)&mem[idx] = meo;
            *(float4*)&spk_out[idx] = spo;
        }
    }
}

// ================= gather-SpMM (binary) =================
template<int NV>
__global__ __launch_bounds__(256)
void spmm_gather(const float* __restrict__ A, const float* __restrict__ WT,
                 const float* __restrict__ bias, float* __restrict__ C,
                 int N, int K) {
    __shared__ short idxs[1536];
    __shared__ int wcnt[8];
    __shared__ int woff[8];
    __shared__ int s_nact;

    const int m = blockIdx.x;
    const int tid = threadIdx.x;
    const int lane = tid & 31;
    const int wid = tid >> 5;
    const float* arow = A + (size_t)m * K;
    const int nch = K >> 5;

    int cnt = 0;
    for (int c = wid; c < nch; c += 8) {
        unsigned mask = __ballot_sync(0xffffffffu, arow[c * 32 + lane] != 0.0f);
        cnt += __popc(mask);
    }
    if (lane == 0) wcnt[wid] = cnt;
    __syncthreads();
    if (tid == 0) {
        int tot = 0;
#pragma unroll
        for (int w = 0; w < 8; w++) { woff[w] = tot; tot += wcnt[w]; }
        s_nact = tot;
    }
    __syncthreads();

    int base = woff[wid];
    for (int c = wid; c < nch; c += 8) {
        int k = c * 32 + lane;
        bool act = (arow[k] != 0.0f);
        unsigned mask = __ballot_sync(0xffffffffu, act);
        if (act) idxs[base + __popc(mask & ((1u << lane) - 1u))] = (short)k;
        base += __popc(mask);
    }
    __syncthreads();

    const int nact = s_nact;
    float acc[NV];
#pragma unroll
    for (int v = 0; v < NV; v++) {
        int n = tid + v * 256;
        acc[v] = (n < N) ? bias[n] : 0.0f;
    }

    int i = 0;
    for (; i + 2 <= nact; i += 2) {
        const float* w0 = WT + (size_t)idxs[i] * N;
        const float* w1 = WT + (size_t)idxs[i + 1] * N;
        float r0[NV], r1[NV];
#pragma unroll
        for (int v = 0; v < NV; v++) {
            int n = tid + v * 256;
            if (n < N) { r0[v] = w0[n]; r1[v] = w1[n]; }
        }
#pragma unroll
        for (int v = 0; v < NV; v++) {
            int n = tid + v * 256;
            if (n < N) { acc[v] += r0[v]; acc[v] += r1[v]; }
        }
    }
    if (i < nact) {
        const float* w0 = WT + (size_t)idxs[i] * N;
#pragma unroll
        for (int v = 0; v < NV; v++) {
            int n = tid + v * 256;
            if (n < N) acc[v] += w0[n];
        }
    }

#pragma unroll
    for (int v = 0; v < NV; v++) {
        int n = tid + v * 256;
        if (n < N) C[(size_t)m * N + n] = acc[v];
    }
}

// ======= rec gather with fused LSM update (N = HID_, NV = 6, exact cover) =======
__global__ __launch_bounds__(256)
void spmm_gather_lsm(const float* __restrict__ A, const float* __restrict__ WT,
                     const float* __restrict__ bias,
                     const float* __restrict__ curr_t, float* __restrict__ syn,
                     float* __restrict__ mem, const float* __restrict__ spk_prev,
                     float* __restrict__ spk_out) {
    const int K = HID_;
    const int N = HID_;
    __shared__ short idxs[1536];
    __shared__ int wcnt[8];
    __shared__ int woff[8];
    __shared__ int s_nact;

    const int m = blockIdx.x;
    const int tid = threadIdx.x;
    const int lane = tid & 31;
    const int wid = tid >> 5;
    const float* arow = A + (size_t)m * K;
    const int nch = K >> 5;

    int cnt = 0;
    for (int c = wid; c < nch; c += 8) {
        unsigned mask = __ballot_sync(0xffffffffu, arow[c * 32 + lane] != 0.0f);
        cnt += __popc(mask);
    }
    if (lane == 0) wcnt[wid] = cnt;
    __syncthreads();
    if (tid == 0) {
        int tot = 0;
#pragma unroll
        for (int w = 0; w < 8; w++) { woff[w] = tot; tot += wcnt[w]; }
        s_nact = tot;
    }
    __syncthreads();

    int base = woff[wid];
    for (int c = wid; c < nch; c += 8) {
        int k = c * 32 + lane;
        bool act = (arow[k] != 0.0f);
        unsigned mask = __ballot_sync(0xffffffffu, act);
        if (act) idxs[base + __popc(mask & ((1u << lane) - 1u))] = (short)k;
        base += __popc(mask);
    }
    __syncthreads();

    const int nact = s_nact;
    float acc[6];
#pragma unroll
    for (int v = 0; v < 6; v++) acc[v] = bias[tid + v * 256];

    int i = 0;
    for (; i + 2 <= nact; i += 2) {
        const float* w0 = WT + (size_t)idxs[i] * N;
        const float* w1 = WT + (size_t)idxs[i + 1] * N;
        float r0[6], r1[6];
#pragma unroll
        for (int v = 0; v < 6; v++) {
            int n = tid + v * 256;
            r0[v] = w0[n]; r1[v] = w1[n];
        }
#pragma unroll
        for (int v = 0; v < 6; v++) { acc[v] += r0[v]; acc[v] += r1[v]; }
    }
    if (i < nact) {
        const float* w0 = WT + (size_t)idxs[i] * N;
#pragma unroll
        for (int v = 0; v < 6; v++) acc[v] += w0[tid + v * 256];
    }

    // fused LSM update (same expression as lsm_step)
#pragma unroll
    for (int v = 0; v < 6; v++) {
        const size_t idx = (size_t)m * N + tid + v * 256;
        float sp = spk_prev[idx];
        float s = 0.9f * syn[idx] + curr_t[idx] + acc[v];
        float mm = 0.8f * mem[idx] + s - sp;
        syn[idx] = s;
        mem[idx] = mm;
        spk_out[idx] = (mm - 1.0f >= 0.0f) ? 1.0f : 0.0f;
    }
}

// ======= fused ARIG fuse + fp gather =======
template<int NV>
__global__ __launch_bounds__(256)
void spmm_gather_fuse(const float* __restrict__ af, const float* __restrict__ lf,
                      const float* __restrict__ ga, const float* __restrict__ gl,
                      const float* __restrict__ WT, const float* __restrict__ bias,
                      float* __restrict__ C, int N, int K) {
    __shared__ short idxs[384];
    __shared__ float vals[384];
    __shared__ int wcnt[8];
    __shared__ int woff[8];
    __shared__ int s_nact;

    const int m = blockIdx.x;
    const int tid = threadIdx.x;
    const int lane = tid & 31;
    const int wid = tid >> 5;
    const float* arow = af + (size_t)m * K;
    const float* lrow = lf + (size_t)m * K;
    const float* garow = ga + (size_t)m * K;
    const float* glrow = gl + (size_t)m * K;
    const int nch = K >> 5;

    int cnt = 0;
    for (int c = wid; c < nch; c += 8) {
        int k = c * 32 + lane;
        bool act = (arow[k] != 0.0f) || (lrow[k] != 0.0f);
        unsigned mask = __ballot_sync(0xffffffffu, act);
        cnt += __popc(mask);
    }
    if (lane == 0) wcnt[wid] = cnt;
    __syncthreads();
    if (tid == 0) {
        int tot = 0;
#pragma unroll
        for (int w = 0; w < 8; w++) { woff[w] = tot; tot += wcnt[w]; }
        s_nact = tot;
    }
    __syncthreads();

    int base = woff[wid];
    for (int c = wid; c < nch; c += 8) {
        int k = c * 32 + lane;
        float a = arow[k];
        float l = lrow[k];
        bool act = (a != 0.0f) || (l != 0.0f);
        unsigned mask = __ballot_sync(0xffffffffu, act);
        if (act) {
            float gate_attn = 1.0f / (1.0f + expf(-glrow[k]));
            float gate_lsm  = 1.0f / (1.0f + expf(-garow[k]));
            float fu = a * gate_attn + l * gate_lsm;
            int p = base + __popc(mask & ((1u << lane) - 1u));
            idxs[p] = (short)k;
            vals[p] = fu;
        }
        base += __popc(mask);
    }
    __syncthreads();

    const int nact = s_nact;
    float acc[NV];
#pragma unroll
    for (int v = 0; v < NV; v++) {
        int n = tid + v * 256;
        acc[v] = (n < N) ? bias[n] : 0.0f;
    }

    for (int i = 0; i < nact; i++) {
        const float* w0 = WT + (size_t)idxs[i] * N;
        const float a = vals[i];
#pragma unroll
        for (int v = 0; v < NV; v++) {
            int n = tid + v * 256;
            if (n < N) acc[v] = fmaf(a, w0[n], acc[v]);
        }
    }

#pragma unroll
    for (int v = 0; v < NV; v++) {
        int n = tid + v * 256;
        if (n < N) C[(size_t)m * N + n] = acc[v];
    }
}

// ---------------- transpose W[Nw,Kw] -> WT[Kw,Nw] ----------------
__global__ void transpose_k(const float* __restrict__ W, float* __restrict__ WT,
                            int Nw, int Kw) {
    __shared__ float t[32][33];
    int bx = blockIdx.x * 32, by = blockIdx.y * 32;
    int x = bx + threadIdx.x;
#pragma unroll
    for (int j = 0; j < 32; j += 8) {
        int y = by + threadIdx.y + j;
        if (y < Nw && x < Kw) t[threadIdx.y + j][threadIdx.x] = W[(size_t)y * Kw + x];
    }
    __syncthreads();
    int x2 = by + threadIdx.x;
#pragma unroll
    for (int j = 0; j < 32; j += 8) {
        int y2 = bx + threadIdx.y + j;
        if (y2 < Kw && x2 < Nw) WT[(size_t)y2 * Nw + x2] = t[threadIdx.x][threadIdx.y + j];
    }
}

// ---------------- LIF scan (in-place), depth-4 prefetch ----------------
__global__ void lif_seq(float* __restrict__ buf, int steps, long stride, long nelem,
                        const float* __restrict__ lif_w, int widx) {
    long idx = (long)blockIdx.x * blockDim.x + threadIdx.x;
    if (idx >= nelem) return;
    const float decay = 1.0f / (1.0f + expf(-lif_w[widx]));
    float v = 0.0f;
    float xs[4];
#pragma unroll
    for (int t = 0; t < 4; t++)
        if (t < steps) xs[t] = buf[(long)t * stride + idx];
    for (int t = 0; t < steps; t++) {
        float x = xs[t & 3];
        if (t + 4 < steps) xs[t & 3] = buf[(long)(t + 4) * stride + idx];
        v = v + (x - v) * decay;
        float s = (v >= 1.0f) ? 1.0f : 0.0f;
        buf[(long)t * stride + idx] = s;
        v *= (1.0f - s);
    }
}

// ---------------- merged q/k/v LIF, 2 columns per thread ----------------
#define HALF_ (NC_ / 2)
__global__ void lif_seq3(float* __restrict__ b0, float* __restrict__ b1,
                         float* __restrict__ b2, const float* __restrict__ lif_w) {
    long idx = (long)blockIdx.x * blockDim.x + threadIdx.x;
    if (idx >= (long)HALF_) return;
    const int which = blockIdx.y;
    float* buf = (which == 0) ? b0 : ((which == 1) ? b1 : b2);
    const float decay = 1.0f / (1.0f + expf(-lif_w[which]));
    const long i0 = idx, i1 = idx + HALF_;
    float v0 = 0.0f, v1 = 0.0f;
    float xs0[4], xs1[4];
#pragma unroll
    for (int t = 0; t < 4; t++) {
        xs0[t] = buf[(long)t * NC_ + i0];
        xs1[t] = buf[(long)t * NC_ + i1];
    }
    for (int t = 0; t < TB_; t++) {
        float x0 = xs0[t & 3], x1 = xs1[t & 3];
        if (t + 4 < TB_) {
            xs0[t & 3] = buf[(long)(t + 4) * NC_ + i0];
            xs1[t & 3] = buf[(long)(t + 4) * NC_ + i1];
        }
        v0 = v0 + (x0 - v0) * decay;
        v1 = v1 + (x1 - v1) * decay;
        float s0 = (v0 >= 1.0f) ? 1.0f : 0.0f;
        float s1 = (v1 >= 1.0f) ? 1.0f : 0.0f;
        buf[(long)t * NC_ + i0] = s0;
        buf[(long)t * NC_ + i1] = s1;
        v0 *= (1.0f - s0);
        v1 *= (1.0f - s1);
    }
}

// ---------------- spiking attention with v-sparsity fast path ----------------
__global__ __launch_bounds__(256)
void attn_kernel(const float* __restrict__ sq, const float* __restrict__ sk,
                 const float* __restrict__ sv, float* __restrict__ abuf) {
    const int tb = blockIdx.x >> 3;
    const int h = blockIdx.x & 7;
    __shared__ unsigned long long qb[N_], kb[N_], vb[N_];
    __shared__ unsigned char cnt[N_ * 200];
    __shared__ int pairs[768];
    __shared__ int s_np;
    const int tid = threadIdx.x;

    for (int i = tid; i < N_; i += 256) { qb[i] = 0ull; kb[i] = 0ull; vb[i] = 0ull; }
    __syncthreads();

    const long base = (long)tb * NC_ + h * D_;
    for (int e = tid; e < N_ * D_; e += 256) {
        int n = e / D_, d = e % D_;
        long off = base + (long)n * C_ + d;
        unsigned long long bit = 1ull << d;
        if (sq[off] != 0.0f) atomicOr(&qb[n], bit);
        if (sk[off] != 0.0f) atomicOr(&kb[n], bit);
        if (sv[off] != 0.0f) atomicOr(&vb[n], bit);
    }
    __syncthreads();

    if (tid == 0) {
        int np = 0;
        for (int m = 0; m < N_; m++) {
            unsigned long long w = vb[m];
            while (w) {
                int d = __ffsll((long long)w) - 1;
                if (np < 768) pairs[np] = (m << 6) | d;
                np++;
                w &= w - 1;
            }
        }
        s_np = np;
    }
    __syncthreads();

    const float scale = 0.14433756729740643f;  // 48^-0.5
    const int np = s_np;
    const long obase = (long)tb * NC_ + h * (D_ * N_);

    if (np <= 768) {
        for (int o = tid; o < N_ * D_; o += 256) {
            int n = o / D_, d = o - n * D_;
            int acc = 0;
            for (int p = 0; p < np; p++) {
                int pm = pairs[p];
                if ((pm & 63) == d) acc += __popcll(qb[n] & kb[pm >> 6]);
            }
            abuf[obase + d * N_ + n] = scale * (float)acc;
        }
        return;
    }

    for (int i = tid; i < N_ * N_; i += 256) {
        int n = i / N_, m = i - n * N_;
        cnt[n * 200 + m] = (unsigned char)__popcll(qb[n] & kb[m]);
    }
    __syncthreads();

    for (int o = tid; o < N_ * D_; o += 256) {
        int n = o / D_, d = o - n * D_;
        const unsigned char* crow = &cnt[n * 200];
        int acc = 0;
#pragma unroll 4
        for (int m = 0; m < N_; m++)
            acc += (int)crow[m] * (int)((vb[m] >> d) & 1ull);
        abuf[obase + d * N_ + n] = scale * (float)acc;
    }
}

// ---------------- LSM step 0 ----------------
__global__ void lsm_step0(const float* __restrict__ curr, const float* __restrict__ rec_b,
                          float* __restrict__ syn, float* __restrict__ mem,
                          float* __restrict__ spk) {
    long idx = (long)blockIdx.x * blockDim.x + threadIdx.x;
    if (idx >= (long)MH_) return;
    int hc = (int)(idx % HID_);
    float s = curr[idx] + rec_b[hc];
    syn[idx] = s;
    mem[idx] = s;
    spk[idx] = (s - 1.0f >= 0.0f) ? 1.0f : 0.0f;
}

// ---------------- BatchNorm stats (deterministic 2-stage) ----------------
__global__ void bn_partial(const float* __restrict__ X, float* __restrict__ part) {
    int c = threadIdx.x;
    long r0 = (long)blockIdx.x * 256;
    float s = 0.0f, s2 = 0.0f;
    for (int r = 0; r < 256; r++) {
        float v = X[(r0 + r) * C_ + c];
        s += v;
        s2 += v * v;
    }
    part[blockIdx.x * 768 + c] = s;
    part[blockIdx.x * 768 + 384 + c] = s2;
}

__global__ void bn_finalize(const float* __restrict__ part, float* __restrict__ stats) {
    int c = threadIdx.x;
    float s = 0.0f, s2 = 0.0f;
    for (int p = 0; p < 98; p++) {
        s += part[p * 768 + c];
        s2 += part[p * 768 + 384 + c];
    }
    const float inv = 1.0f / 25088.0f;
    float m = s * inv;
    float var = s2 * inv - m * m;
    stats[c] = m;
    stats[384 + c] = 1.0f / sqrtf(var + 1e-5f);
}

// ---------------- fused BN-apply + 4-step LIF (+ optional residual) ----------------
__global__ void bn_lif4(const float* __restrict__ lin, float* __restrict__ out,
                        const float* __restrict__ stats,
                        const float* __restrict__ gamma, const float* __restrict__ beta,
                        const float* __restrict__ lif_w, int widx,
                        const float* __restrict__ xadd) {
    long idx = (long)blockIdx.x * blockDim.x + threadIdx.x;
    if (idx >= (long)BNC_) return;
    int c = (int)(idx % C_);
    float mu = stats[c], rstd = stats[384 + c];
    float gg = gamma[c], bb = beta[c];
    float decay = 1.0f / (1.0f + expf(-lif_w[widx]));
    float v = 0.0f;
    float xs[4];
#pragma unroll
    for (int t = 0; t < 4; t++) xs[t] = lin[(long)t * BNC_ + idx];
#pragma unroll
    for (int t = 0; t < 4; t++) {
        long o = (long)t * BNC_ + idx;
        float xv = (xs[t] - mu) * rstd * gg + bb;
        v = v + (xv - v) * decay;
        float s = (v >= 1.0f) ? 1.0f : 0.0f;
        v *= (1.0f - s);
        if (xadd) out[o] = xadd[o] + s;
        else      out[o] = s;
    }
}

// ---------------- launch ----------------
extern "C" void kernel_launch(void* const* d_in, const int* in_sizes, int n_in,
                              void* d_out, int out_size) {
    const float* x      = (const float*)d_in[0];
    const float* q_w    = (const float*)d_in[1];
    const float* q_b    = (const float*)d_in[2];
    const float* k_w    = (const float*)d_in[3];
    const float* k_b    = (const float*)d_in[4];
    const float* v_w    = (const float*)d_in[5];
    const float* v_b    = (const float*)d_in[6];
    const float* ap_w   = (const float*)d_in[7];
    const float* ap_b   = (const float*)d_in[8];
    const float* fc1_w  = (const float*)d_in[9];
    const float* fc1_b  = (const float*)d_in[10];
    const float* rec_w  = (const float*)d_in[11];
    const float* rec_b  = (const float*)d_in[12];
    const float* fc2_w  = (const float*)d_in[13];
    const float* fc2_b  = (const float*)d_in[14];
    const float* bnl_g  = (const float*)d_in[15];
    const float* bnl_b  = (const float*)d_in[16];
    const float* watt_w = (const float*)d_in[17];
    const float* watt_b = (const float*)d_in[18];
    const float* wlsm_w = (const float*)d_in[19];
    const float* wlsm_b = (const float*)d_in[20];
    const float* fp_w   = (const float*)d_in[21];
    const float* fp_b   = (const float*)d_in[22];
    const float* bnf_g  = (const float*)d_in[23];
    const float* bnf_b  = (const float*)d_in[24];
    const float* lif_w  = (const float*)d_in[25];
    float* out = (float*)d_out;

    float *bq, *bk, *bv, *ab, *af, *curr, *syn, *mem, *spk, *l, *ga, *gl, *o, *part, *stats;
    float *apT, *watT, *wlsT, *fpT, *recT, *fc2T;
    cudaGetSymbolAddress((void**)&bq, g_bq);
    cudaGetSymbolAddress((void**)&bk, g_bk);
    cudaGetSymbolAddress((void**)&bv, g_bv);
    cudaGetSymbolAddress((void**)&ab, g_ab);
    cudaGetSymbolAddress((void**)&af, g_af);
    cudaGetSymbolAddress((void**)&curr, g_curr);
    cudaGetSymbolAddress((void**)&syn, g_syn);
    cudaGetSymbolAddress((void**)&mem, g_mem);
    cudaGetSymbolAddress((void**)&spk, g_spk);
    cudaGetSymbolAddress((void**)&l, g_l);
    cudaGetSymbolAddress((void**)&ga, g_ga);
    cudaGetSymbolAddress((void**)&gl, g_gl);
    cudaGetSymbolAddress((void**)&o, g_o);
    cudaGetSymbolAddress((void**)&part, g_part);
    cudaGetSymbolAddress((void**)&stats, g_stats);
    cudaGetSymbolAddress((void**)&apT, g_apT);
    cudaGetSymbolAddress((void**)&watT, g_watT);
    cudaGetSymbolAddress((void**)&wlsT, g_wlsT);
    cudaGetSymbolAddress((void**)&fpT, g_fpT);
    cudaGetSymbolAddress((void**)&recT, g_recT);
    cudaGetSymbolAddress((void**)&fc2T, g_fc2T);

    const dim3 gC(C_ / BN, TBN_ / BM);     // (3, 196)
    const dim3 gH(HID_ / BN, TBN_ / BM);   // (12, 196) fc1
    const dim3 gR(HID_ / BN, BN_ / BM);    // (12, 49)  rec dense
    const int nb75k = (NC_ + 255) / 256;
    const int nbHALF = (HALF_ + 255) / 256;  // 147
    const int nbBNC = (BNC_ + 255) / 256;
    const int nbMH  = (MH_ + 255) / 256;
    const dim3 tb32(32, 8);
    const dim3 gT384(C_ / 32, C_ / 32);
    const dim3 gT1536(HID_ / 32, HID_ / 32);
    const dim3 gTfc2(HID_ / 32, C_ / 32);

    // ---- prep: weight transposes ----
    transpose_k<<<gT384, tb32>>>(ap_w, apT, C_, C_);
    transpose_k<<<gT384, tb32>>>(watt_w, watT, C_, C_);
    transpose_k<<<gT384, tb32>>>(wlsm_w, wlsT, C_, C_);
    transpose_k<<<gT384, tb32>>>(fp_w, fpT, C_, C_);
    transpose_k<<<gT1536, tb32>>>(rec_w, recT, HID_, HID_);
    transpose_k<<<gTfc2, tb32>>>(fc2_w, fc2T, C_, HID_);

    // --- SSA branch (separate GEMMs, R12-proven) ---
    sgemm_nt<<<gC, 256>>>(x, q_w, q_b, bq, TBN_, C_, C_);
    sgemm_nt<<<gC, 256>>>(x, k_w, k_b, bk, TBN_, C_, C_);
    sgemm_nt<<<gC, 256>>>(x, v_w, v_b, bv, TBN_, C_, C_);
    lif_seq3<<<dim3(nbHALF, 3), 256>>>(bq, bk, bv, lif_w);
    attn_kernel<<<TB_ * H_, 256>>>(bq, bk, bv, ab);
    lif_seq<<<nbBNC, 256>>>(ab, T_, BNC_, BNC_, lif_w, 3);
    spmm_gather<2><<<TBN_, 256>>>(ab, apT, ap_b, af, C_, C_);
    lif_seq<<<nb75k, 256>>>(af, TB_, NC_, NC_, lif_w, 4);

    // --- LSM branch: fc1 then fused rec+LSM steps ---
    sgemm_nt<<<gH, 256>>>(x, fc1_w, fc1_b, curr, TBN_, HID_, C_);
    lsm_step0<<<nbMH, 256>>>(curr, rec_b, syn, mem, spk);
    // t=1, t=2: gather with fused LSM update
    spmm_gather_lsm<<<BN_, 256>>>(spk, recT, rec_b,
                                  curr + (size_t)MH_, syn, mem,
                                  spk, spk + (size_t)MH_);
    spmm_gather_lsm<<<BN_, 256>>>(spk + (size_t)MH_, recT, rec_b,
                                  curr + 2 * (size_t)MH_, syn, mem,
                                  spk + (size_t)MH_, spk + 2 * (size_t)MH_);
    // t=3: dense GEMM with fused LSM update
    sgemm_nt_lsm<<<gR, 256>>>(spk + 2 * (size_t)MH_, rec_w, rec_b,
                              curr + 3 * (size_t)MH_, syn, mem,
                              spk + 2 * (size_t)MH_, spk + 3 * (size_t)MH_,
                              BN_, HID_);

    // fc2 split by t: t0/t1 gather, t2+t3 dense
    spmm_gather<2><<<BN_, 256>>>(spk, fc2T, fc2_b, l, C_, HID_);
    spmm_gather<2><<<BN_, 256>>>(spk + (size_t)MH_, fc2T, fc2_b,
                                 l + (size_t)BN_ * C_, C_, HID_);
    sgemm_nt<<<dim3(C_ / BN, (2 * BN_) / BM), 256>>>(spk + 2 * (size_t)MH_, fc2_w, fc2_b,
                                                     l + 2 * (size_t)BN_ * C_,
                                                     2 * BN_, C_, HID_);
    bn_partial<<<98, 384>>>(l, part);
    bn_finalize<<<1, 384>>>(part, stats);
    bn_lif4<<<nbBNC, 256>>>(l, l, stats, bnl_g, bnl_b, lif_w, 5, nullptr);

    // --- ARIG fusion ---
    spmm_gather<2><<<TBN_, 256>>>(af, watT, watt_b, ga, C_, C_);
    spmm_gather<2><<<TBN_, 256>>>(l, wlsT, wlsm_b, gl, C_, C_);
    spmm_gather_fuse<2><<<TBN_, 256>>>(af, l, ga, gl, fpT, fp_b, o, C_, C_);
    bn_partial<<<98, 384>>>(o, part);
    bn_finalize<<<1, 384>>>(part, stats);
    bn_lif4<<<nbBNC, 256>>>(o, out, stats, bnf_g, bnf_b, lif_w, 6, x);
}

// round 15
// speedup vs baseline: 1.0729x; 1.0480x over previous
#include <cuda_runtime.h>
#include <math.h>
#include <stdint.h>

// ---------------- problem constants ----------------
#define T_    4
#define B_    32
#define N_    196
#define C_    384
#define H_    8
#define D_    48
#define HID_  1536
#define TB_   128           // T*B
#define NC_   75264         // N*C
#define BNC_  2408448       // B*N*C
#define TBN_  25088         // T*B*N
#define BN_   6272          // B*N
#define MH_   9633792       // BN_*HID_ == TBN_*C_
#define CC_   (C_ * C_)
#define HC_   (HID_ * C_)
#define HH_   (HID_ * HID_)

// ---------------- scratch (device globals; no runtime alloc allowed) ----------------
__device__ float g_bq[MH_];
__device__ float g_bk[MH_];
__device__ float g_bv[MH_];
__device__ float g_ab[MH_];
__device__ float g_af[MH_];
__device__ float g_curr[4 * MH_];
__device__ float g_syn[MH_];
__device__ float g_mem[MH_];
__device__ float g_spk[4 * MH_];
__device__ float g_l[MH_];
__device__ float g_ga[MH_];
__device__ float g_gl[MH_];
__device__ float g_o[MH_];
__device__ float g_part[98 * 768];
__device__ float g_stats[768];   // [0:384) mu, [384:768) rstd
// transposed weights for gather-SpMM
__device__ float g_apT[CC_];
__device__ float g_watT[CC_];
__device__ float g_wlsT[CC_];
__device__ float g_fpT[CC_];
__device__ float g_recT[HH_];
__device__ float g_fc2T[HC_];

// ---------------- f32x2 packed-FMA helpers ----------------
#define FMA2(D, A, B) \
    asm("fma.rn.f32x2 %0, %1, %2, %0;" : "+l"(D) : "l"(A), "l"(B))
#define PACK2(P, X, Y) \
    asm("mov.b64 %0, {%1, %2};" : "=l"(P) : "f"(X), "f"(Y))
#define UNPACK2(X, Y, P) \
    asm("mov.b64 {%0, %1}, %2;" : "=f"(X), "=f"(Y) : "l"(P))

#define BM 128
#define BN 128
#define BK 16

// ================= SGEMM2 core (BK=16, round-11 proven) =================
struct AccP { unsigned long long p[8][4]; };

__device__ __forceinline__ void sgemm_core(
    const float* __restrict__ A, const float* __restrict__ W,
    int K, int bm, int bn, int tid,
    float As[2][BK][BM], float Bs[2][BK][BN], AccP& acc) {
    const int lrow = tid >> 2;
    const int lq = (tid & 3) * 4;
    const float* Ap0 = A + (size_t)(bm + lrow) * K + lq;
    const float* Ap1 = A + (size_t)(bm + lrow + 64) * K + lq;
    const float* Wp0 = W + (size_t)(bn + lrow) * K + lq;
    const float* Wp1 = W + (size_t)(bn + lrow + 64) * K + lq;

    const int tx = tid & 15;
    const int ty = tid >> 4;

#pragma unroll
    for (int i = 0; i < 8; i++)
#pragma unroll
        for (int jp = 0; jp < 4; jp++) acc.p[i][jp] = 0ull;

    float4 a0 = *(const float4*)Ap0;
    float4 a1 = *(const float4*)Ap1;
    float4 w0 = *(const float4*)Wp0;
    float4 w1 = *(const float4*)Wp1;
    As[0][lq + 0][lrow] = a0.x; As[0][lq + 1][lrow] = a0.y;
    As[0][lq + 2][lrow] = a0.z; As[0][lq + 3][lrow] = a0.w;
    As[0][lq + 0][lrow + 64] = a1.x; As[0][lq + 1][lrow + 64] = a1.y;
    As[0][lq + 2][lrow + 64] = a1.z; As[0][lq + 3][lrow + 64] = a1.w;
    Bs[0][lq + 0][lrow] = w0.x; Bs[0][lq + 1][lrow] = w0.y;
    Bs[0][lq + 2][lrow] = w0.z; Bs[0][lq + 3][lrow] = w0.w;
    Bs[0][lq + 0][lrow + 64] = w1.x; Bs[0][lq + 1][lrow + 64] = w1.y;
    Bs[0][lq + 2][lrow + 64] = w1.z; Bs[0][lq + 3][lrow + 64] = w1.w;
    __syncthreads();

    const int nk = K / BK;
    for (int kt = 0; kt < nk; kt++) {
        const int cur = kt & 1;
        if (kt + 1 < nk) {
            const size_t off = (size_t)(kt + 1) * BK;
            a0 = *(const float4*)(Ap0 + off);
            a1 = *(const float4*)(Ap1 + off);
            w0 = *(const float4*)(Wp0 + off);
            w1 = *(const float4*)(Wp1 + off);
        }
#pragma unroll
        for (int kk = 0; kk < BK; kk++) {
            float4 av0 = *(const float4*)&As[cur][kk][ty * 4];
            float4 av1 = *(const float4*)&As[cur][kk][ty * 4 + 64];
            float4 bv0 = *(const float4*)&Bs[cur][kk][tx * 4];
            float4 bv1 = *(const float4*)&Bs[cur][kk][tx * 4 + 64];
            unsigned long long bp[4];
            PACK2(bp[0], bv0.x, bv0.y);
            PACK2(bp[1], bv0.z, bv0.w);
            PACK2(bp[2], bv1.x, bv1.y);
            PACK2(bp[3], bv1.z, bv1.w);
            float avs[8] = {av0.x, av0.y, av0.z, av0.w, av1.x, av1.y, av1.z, av1.w};
#pragma unroll
            for (int i = 0; i < 8; i++) {
                unsigned long long ap;
                PACK2(ap, avs[i], avs[i]);
                FMA2(acc.p[i][0], ap, bp[0]);
                FMA2(acc.p[i][1], ap, bp[1]);
                FMA2(acc.p[i][2], ap, bp[2]);
                FMA2(acc.p[i][3], ap, bp[3]);
            }
        }
        if (kt + 1 < nk) {
            const int nxt = cur ^ 1;
            As[nxt][lq + 0][lrow] = a0.x; As[nxt][lq + 1][lrow] = a0.y;
            As[nxt][lq + 2][lrow] = a0.z; As[nxt][lq + 3][lrow] = a0.w;
            As[nxt][lq + 0][lrow + 64] = a1.x; As[nxt][lq + 1][lrow + 64] = a1.y;
            As[nxt][lq + 2][lrow + 64] = a1.z; As[nxt][lq + 3][lrow + 64] = a1.w;
            Bs[nxt][lq + 0][lrow] = w0.x; Bs[nxt][lq + 1][lrow] = w0.y;
            Bs[nxt][lq + 2][lrow] = w0.z; Bs[nxt][lq + 3][lrow] = w0.w;
            Bs[nxt][lq + 0][lrow + 64] = w1.x; Bs[nxt][lq + 1][lrow + 64] = w1.y;
            Bs[nxt][lq + 2][lrow + 64] = w1.z; Bs[nxt][lq + 3][lrow + 64] = w1.w;
            __syncthreads();
        }
    }
}

// ---- generic GEMM: C[M,N] = A @ W^T + bias ----
__global__ __launch_bounds__(256, 2)
void sgemm_nt(const float* __restrict__ A, const float* __restrict__ W,
              const float* __restrict__ bias, float* __restrict__ C,
              int M, int N, int K) {
    __shared__ float As[2][BK][BM];
    __shared__ float Bs[2][BK][BN];
    const int tid = threadIdx.x;
    const int bm = blockIdx.y * BM;
    const int bn = blockIdx.x * BN;
    const int tx = tid & 15;
    const int ty = tid >> 4;
    AccP acc;
    sgemm_core(A, W, K, bm, bn, tid, As, Bs, acc);

#pragma unroll
    for (int i = 0; i < 8; i++) {
        const int row = bm + ty * 4 + (i & 3) + ((i >> 2) << 6);
#pragma unroll
        for (int jb = 0; jb < 2; jb++) {
            const int col = bn + tx * 4 + jb * 64;
            float4 bv4 = *(const float4*)&bias[col];
            float c0, c1, c2, c3;
            UNPACK2(c0, c1, acc.p[i][jb * 2 + 0]);
            UNPACK2(c2, c3, acc.p[i][jb * 2 + 1]);
            float4 v;
            v.x = c0 + bv4.x;
            v.y = c1 + bv4.y;
            v.z = c2 + bv4.z;
            v.w = c3 + bv4.w;
            *(float4*)&C[(size_t)row * N + col] = v;
        }
    }
}

// ---- dense rec GEMM with fused LSM update (t=3 step); N = HID_ ----
__global__ __launch_bounds__(256, 2)
void sgemm_nt_lsm(const float* __restrict__ A, const float* __restrict__ W,
                  const float* __restrict__ bias,
                  const float* __restrict__ curr_t, float* __restrict__ syn,
                  float* __restrict__ mem, const float* __restrict__ spk_prev,
                  float* __restrict__ spk_out, int M, int K) {
    __shared__ float As[2][BK][BM];
    __shared__ float Bs[2][BK][BN];
    const int tid = threadIdx.x;
    const int bm = blockIdx.y * BM;
    const int bn = blockIdx.x * BN;
    const int tx = tid & 15;
    const int ty = tid >> 4;
    AccP acc;
    sgemm_core(A, W, K, bm, bn, tid, As, Bs, acc);

#pragma unroll
    for (int i = 0; i < 8; i++) {
        const int row = bm + ty * 4 + (i & 3) + ((i >> 2) << 6);
#pragma unroll
        for (int jb = 0; jb < 2; jb++) {
            const int col = bn + tx * 4 + jb * 64;
            const size_t idx = (size_t)row * HID_ + col;
            float4 bv4 = *(const float4*)&bias[col];
            float c0, c1, c2, c3;
            UNPACK2(c0, c1, acc.p[i][jb * 2 + 0]);
            UNPACK2(c2, c3, acc.p[i][jb * 2 + 1]);
            float Rv[4] = {c0 + bv4.x, c1 + bv4.y, c2 + bv4.z, c3 + bv4.w};
            float4 sy = *(const float4*)&syn[idx];
            float4 me = *(const float4*)&mem[idx];
            float4 cu = *(const float4*)&curr_t[idx];
            float4 sp = *(const float4*)&spk_prev[idx];
            float4 syo, meo, spo;
            float s, mm;
            s = 0.9f * sy.x + cu.x + Rv[0]; mm = 0.8f * me.x + s - sp.x;
            syo.x = s; meo.x = mm; spo.x = (mm - 1.0f >= 0.0f) ? 1.0f : 0.0f;
            s = 0.9f * sy.y + cu.y + Rv[1]; mm = 0.8f * me.y + s - sp.y;
            syo.y = s; meo.y = mm; spo.y = (mm - 1.0f >= 0.0f) ? 1.0f : 0.0f;
            s = 0.9f * sy.z + cu.z + Rv[2]; mm = 0.8f * me.z + s - sp.z;
            syo.z = s; meo.z = mm; spo.z = (mm - 1.0f >= 0.0f) ? 1.0f : 0.0f;
            s = 0.9f * sy.w + cu.w + Rv[3]; mm = 0.8f * me.w + s - sp.w;
            syo.w = s; meo.w = mm; spo.w = (mm - 1.0f >= 0.0f) ? 1.0f : 0.0f;
            *(float4*)&syn[idx] = syo;
            *(float4*)&mem[idx] = meo;
            *(float4*)&spk_out[idx] = spo;
        }
    }
}

// ================= gather-SpMM (binary) =================
template<int NV>
__global__ __launch_bounds__(256)
void spmm_gather(const float* __restrict__ A, const float* __restrict__ WT,
                 const float* __restrict__ bias, float* __restrict__ C,
                 int N, int K) {
    __shared__ short idxs[1536];
    __shared__ int wcnt[8];
    __shared__ int woff[8];
    __shared__ int s_nact;

    const int m = blockIdx.x;
    const int tid = threadIdx.x;
    const int lane = tid & 31;
    const int wid = tid >> 5;
    const float* arow = A + (size_t)m * K;
    const int nch = K >> 5;

    int cnt = 0;
    for (int c = wid; c < nch; c += 8) {
        unsigned mask = __ballot_sync(0xffffffffu, arow[c * 32 + lane] != 0.0f);
        cnt += __popc(mask);
    }
    if (lane == 0) wcnt[wid] = cnt;
    __syncthreads();
    if (tid == 0) {
        int tot = 0;
#pragma unroll
        for (int w = 0; w < 8; w++) { woff[w] = tot; tot += wcnt[w]; }
        s_nact = tot;
    }
    __syncthreads();

    int base = woff[wid];
    for (int c = wid; c < nch; c += 8) {
        int k = c * 32 + lane;
        bool act = (arow[k] != 0.0f);
        unsigned mask = __ballot_sync(0xffffffffu, act);
        if (act) idxs[base + __popc(mask & ((1u << lane) - 1u))] = (short)k;
        base += __popc(mask);
    }
    __syncthreads();

    const int nact = s_nact;
    float acc[NV];
#pragma unroll
    for (int v = 0; v < NV; v++) {
        int n = tid + v * 256;
        acc[v] = (n < N) ? bias[n] : 0.0f;
    }

    int i = 0;
    for (; i + 2 <= nact; i += 2) {
        const float* w0 = WT + (size_t)idxs[i] * N;
        const float* w1 = WT + (size_t)idxs[i + 1] * N;
        float r0[NV], r1[NV];
#pragma unroll
        for (int v = 0; v < NV; v++) {
            int n = tid + v * 256;
            if (n < N) { r0[v] = w0[n]; r1[v] = w1[n]; }
        }
#pragma unroll
        for (int v = 0; v < NV; v++) {
            int n = tid + v * 256;
            if (n < N) { acc[v] += r0[v]; acc[v] += r1[v]; }
        }
    }
    if (i < nact) {
        const float* w0 = WT + (size_t)idxs[i] * N;
#pragma unroll
        for (int v = 0; v < NV; v++) {
            int n = tid + v * 256;
            if (n < N) acc[v] += w0[n];
        }
    }

#pragma unroll
    for (int v = 0; v < NV; v++) {
        int n = tid + v * 256;
        if (n < N) C[(size_t)m * N + n] = acc[v];
    }
}

// ======= rec gather with fused LSM update (N = HID_, NV = 6, exact cover) =======
__global__ __launch_bounds__(256)
void spmm_gather_lsm(const float* __restrict__ A, const float* __restrict__ WT,
                     const float* __restrict__ bias,
                     const float* __restrict__ curr_t, float* __restrict__ syn,
                     float* __restrict__ mem, const float* __restrict__ spk_prev,
                     float* __restrict__ spk_out) {
    const int K = HID_;
    const int N = HID_;
    __shared__ short idxs[1536];
    __shared__ int wcnt[8];
    __shared__ int woff[8];
    __shared__ int s_nact;

    const int m = blockIdx.x;
    const int tid = threadIdx.x;
    const int lane = tid & 31;
    const int wid = tid >> 5;
    const float* arow = A + (size_t)m * K;
    const int nch = K >> 5;

    int cnt = 0;
    for (int c = wid; c < nch; c += 8) {
        unsigned mask = __ballot_sync(0xffffffffu, arow[c * 32 + lane] != 0.0f);
        cnt += __popc(mask);
    }
    if (lane == 0) wcnt[wid] = cnt;
    __syncthreads();
    if (tid == 0) {
        int tot = 0;
#pragma unroll
        for (int w = 0; w < 8; w++) { woff[w] = tot; tot += wcnt[w]; }
        s_nact = tot;
    }
    __syncthreads();

    int base = woff[wid];
    for (int c = wid; c < nch; c += 8) {
        int k = c * 32 + lane;
        bool act = (arow[k] != 0.0f);
        unsigned mask = __ballot_sync(0xffffffffu, act);
        if (act) idxs[base + __popc(mask & ((1u << lane) - 1u))] = (short)k;
        base += __popc(mask);
    }
    __syncthreads();

    const int nact = s_nact;
    float acc[6];
#pragma unroll
    for (int v = 0; v < 6; v++) acc[v] = bias[tid + v * 256];

    int i = 0;
    for (; i + 2 <= nact; i += 2) {
        const float* w0 = WT + (size_t)idxs[i] * N;
        const float* w1 = WT + (size_t)idxs[i + 1] * N;
        float r0[6], r1[6];
#pragma unroll
        for (int v = 0; v < 6; v++) {
            int n = tid + v * 256;
            r0[v] = w0[n]; r1[v] = w1[n];
        }
#pragma unroll
        for (int v = 0; v < 6; v++) { acc[v] += r0[v]; acc[v] += r1[v]; }
    }
    if (i < nact) {
        const float* w0 = WT + (size_t)idxs[i] * N;
#pragma unroll
        for (int v = 0; v < 6; v++) acc[v] += w0[tid + v * 256];
    }

#pragma unroll
    for (int v = 0; v < 6; v++) {
        const size_t idx = (size_t)m * N + tid + v * 256;
        float sp = spk_prev[idx];
        float s = 0.9f * syn[idx] + curr_t[idx] + acc[v];
        float mm = 0.8f * mem[idx] + s - sp;
        syn[idx] = s;
        mem[idx] = mm;
        spk_out[idx] = (mm - 1.0f >= 0.0f) ? 1.0f : 0.0f;
    }
}

// ======= fused ARIG fuse + fp gather =======
template<int NV>
__global__ __launch_bounds__(256)
void spmm_gather_fuse(const float* __restrict__ af, const float* __restrict__ lf,
                      const float* __restrict__ ga, const float* __restrict__ gl,
                      const float* __restrict__ WT, const float* __restrict__ bias,
                      float* __restrict__ C, int N, int K) {
    __shared__ short idxs[384];
    __shared__ float vals[384];
    __shared__ int wcnt[8];
    __shared__ int woff[8];
    __shared__ int s_nact;

    const int m = blockIdx.x;
    const int tid = threadIdx.x;
    const int lane = tid & 31;
    const int wid = tid >> 5;
    const float* arow = af + (size_t)m * K;
    const float* lrow = lf + (size_t)m * K;
    const float* garow = ga + (size_t)m * K;
    const float* glrow = gl + (size_t)m * K;
    const int nch = K >> 5;

    int cnt = 0;
    for (int c = wid; c < nch; c += 8) {
        int k = c * 32 + lane;
        bool act = (arow[k] != 0.0f) || (lrow[k] != 0.0f);
        unsigned mask = __ballot_sync(0xffffffffu, act);
        cnt += __popc(mask);
    }
    if (lane == 0) wcnt[wid] = cnt;
    __syncthreads();
    if (tid == 0) {
        int tot = 0;
#pragma unroll
        for (int w = 0; w < 8; w++) { woff[w] = tot; tot += wcnt[w]; }
        s_nact = tot;
    }
    __syncthreads();

    int base = woff[wid];
    for (int c = wid; c < nch; c += 8) {
        int k = c * 32 + lane;
        float a = arow[k];
        float l = lrow[k];
        bool act = (a != 0.0f) || (l != 0.0f);
        unsigned mask = __ballot_sync(0xffffffffu, act);
        if (act) {
            float gate_attn = 1.0f / (1.0f + expf(-glrow[k]));
            float gate_lsm  = 1.0f / (1.0f + expf(-garow[k]));
            float fu = a * gate_attn + l * gate_lsm;
            int p = base + __popc(mask & ((1u << lane) - 1u));
            idxs[p] = (short)k;
            vals[p] = fu;
        }
        base += __popc(mask);
    }
    __syncthreads();

    const int nact = s_nact;
    float acc[NV];
#pragma unroll
    for (int v = 0; v < NV; v++) {
        int n = tid + v * 256;
        acc[v] = (n < N) ? bias[n] : 0.0f;
    }

    for (int i = 0; i < nact; i++) {
        const float* w0 = WT + (size_t)idxs[i] * N;
        const float a = vals[i];
#pragma unroll
        for (int v = 0; v < NV; v++) {
            int n = tid + v * 256;
            if (n < N) acc[v] = fmaf(a, w0[n], acc[v]);
        }
    }

#pragma unroll
    for (int v = 0; v < NV; v++) {
        int n = tid + v * 256;
        if (n < N) C[(size_t)m * N + n] = acc[v];
    }
}

// ---------------- transpose W[Nw,Kw] -> WT[Kw,Nw] ----------------
__global__ void transpose_k(const float* __restrict__ W, float* __restrict__ WT,
                            int Nw, int Kw) {
    __shared__ float t[32][33];
    int bx = blockIdx.x * 32, by = blockIdx.y * 32;
    int x = bx + threadIdx.x;
#pragma unroll
    for (int j = 0; j < 32; j += 8) {
        int y = by + threadIdx.y + j;
        if (y < Nw && x < Kw) t[threadIdx.y + j][threadIdx.x] = W[(size_t)y * Kw + x];
    }
    __syncthreads();
    int x2 = by + threadIdx.x;
#pragma unroll
    for (int j = 0; j < 32; j += 8) {
        int y2 = bx + threadIdx.y + j;
        if (y2 < Kw && x2 < Nw) WT[(size_t)y2 * Nw + x2] = t[threadIdx.x][threadIdx.y + j];
    }
}

// ---------------- LIF scan (in-place), depth-4 prefetch ----------------
__global__ void lif_seq(float* __restrict__ buf, int steps, long stride, long nelem,
                        const float* __restrict__ lif_w, int widx) {
    long idx = (long)blockIdx.x * blockDim.x + threadIdx.x;
    if (idx >= nelem) return;
    const float decay = 1.0f / (1.0f + expf(-lif_w[widx]));
    float v = 0.0f;
    float xs[4];
#pragma unroll
    for (int t = 0; t < 4; t++)
        if (t < steps) xs[t] = buf[(long)t * stride + idx];
    for (int t = 0; t < steps; t++) {
        float x = xs[t & 3];
        if (t + 4 < steps) xs[t & 3] = buf[(long)(t + 4) * stride + idx];
        v = v + (x - v) * decay;
        float s = (v >= 1.0f) ? 1.0f : 0.0f;
        buf[(long)t * stride + idx] = s;
        v *= (1.0f - s);
    }
}

// ---------------- merged q/k/v LIF, 2 columns per thread ----------------
#define HALF_ (NC_ / 2)
__global__ void lif_seq3(float* __restrict__ b0, float* __restrict__ b1,
                         float* __restrict__ b2, const float* __restrict__ lif_w) {
    long idx = (long)blockIdx.x * blockDim.x + threadIdx.x;
    if (idx >= (long)HALF_) return;
    const int which = blockIdx.y;
    float* buf = (which == 0) ? b0 : ((which == 1) ? b1 : b2);
    const float decay = 1.0f / (1.0f + expf(-lif_w[which]));
    const long i0 = idx, i1 = idx + HALF_;
    float v0 = 0.0f, v1 = 0.0f;
    float xs0[4], xs1[4];
#pragma unroll
    for (int t = 0; t < 4; t++) {
        xs0[t] = buf[(long)t * NC_ + i0];
        xs1[t] = buf[(long)t * NC_ + i1];
    }
    for (int t = 0; t < TB_; t++) {
        float x0 = xs0[t & 3], x1 = xs1[t & 3];
        if (t + 4 < TB_) {
            xs0[t & 3] = buf[(long)(t + 4) * NC_ + i0];
            xs1[t & 3] = buf[(long)(t + 4) * NC_ + i1];
        }
        v0 = v0 + (x0 - v0) * decay;
        v1 = v1 + (x1 - v1) * decay;
        float s0 = (v0 >= 1.0f) ? 1.0f : 0.0f;
        float s1 = (v1 >= 1.0f) ? 1.0f : 0.0f;
        buf[(long)t * NC_ + i0] = s0;
        buf[(long)t * NC_ + i1] = s1;
        v0 *= (1.0f - s0);
        v1 *= (1.0f - s1);
    }
}

// ---------------- spiking attention with v-sparsity fast path ----------------
__global__ __launch_bounds__(256)
void attn_kernel(const float* __restrict__ sq, const float* __restrict__ sk,
                 const float* __restrict__ sv, float* __restrict__ abuf) {
    const int tb = blockIdx.x >> 3;
    const int h = blockIdx.x & 7;
    __shared__ unsigned long long qb[N_], kb[N_], vb[N_];
    __shared__ unsigned char cnt[N_ * 200];
    __shared__ int pairs[768];
    __shared__ int s_np;
    const int tid = threadIdx.x;

    for (int i = tid; i < N_; i += 256) { qb[i] = 0ull; kb[i] = 0ull; vb[i] = 0ull; }
    __syncthreads();

    const long base = (long)tb * NC_ + h * D_;
    for (int e = tid; e < N_ * D_; e += 256) {
        int n = e / D_, d = e % D_;
        long off = base + (long)n * C_ + d;
        unsigned long long bit = 1ull << d;
        if (sq[off] != 0.0f) atomicOr(&qb[n], bit);
        if (sk[off] != 0.0f) atomicOr(&kb[n], bit);
        if (sv[off] != 0.0f) atomicOr(&vb[n], bit);
    }
    __syncthreads();

    if (tid == 0) {
        int np = 0;
        for (int m = 0; m < N_; m++) {
            unsigned long long w = vb[m];
            while (w) {
                int d = __ffsll((long long)w) - 1;
                if (np < 768) pairs[np] = (m << 6) | d;
                np++;
                w &= w - 1;
            }
        }
        s_np = np;
    }
    __syncthreads();

    const float scale = 0.14433756729740643f;  // 48^-0.5
    const int np = s_np;
    const long obase = (long)tb * NC_ + h * (D_ * N_);

    if (np <= 768) {
        for (int o = tid; o < N_ * D_; o += 256) {
            int n = o / D_, d = o - n * D_;
            int acc = 0;
            for (int p = 0; p < np; p++) {
                int pm = pairs[p];
                if ((pm & 63) == d) acc += __popcll(qb[n] & kb[pm >> 6]);
            }
            abuf[obase + d * N_ + n] = scale * (float)acc;
        }
        return;
    }

    for (int i = tid; i < N_ * N_; i += 256) {
        int n = i / N_, m = i - n * N_;
        cnt[n * 200 + m] = (unsigned char)__popcll(qb[n] & kb[m]);
    }
    __syncthreads();

    for (int o = tid; o < N_ * D_; o += 256) {
        int n = o / D_, d = o - n * D_;
        const unsigned char* crow = &cnt[n * 200];
        int acc = 0;
#pragma unroll 4
        for (int m = 0; m < N_; m++)
            acc += (int)crow[m] * (int)((vb[m] >> d) & 1ull);
        abuf[obase + d * N_ + n] = scale * (float)acc;
    }
}

// ---------------- LSM step 0 ----------------
__global__ void lsm_step0(const float* __restrict__ curr, const float* __restrict__ rec_b,
                          float* __restrict__ syn, float* __restrict__ mem,
                          float* __restrict__ spk) {
    long idx = (long)blockIdx.x * blockDim.x + threadIdx.x;
    if (idx >= (long)MH_) return;
    int hc = (int)(idx % HID_);
    float s = curr[idx] + rec_b[hc];
    syn[idx] = s;
    mem[idx] = s;
    spk[idx] = (s - 1.0f >= 0.0f) ? 1.0f : 0.0f;
}

// ---------------- BatchNorm stats (deterministic 2-stage) ----------------
__global__ void bn_partial(const float* __restrict__ X, float* __restrict__ part) {
    int c = threadIdx.x;
    long r0 = (long)blockIdx.x * 256;
    float s = 0.0f, s2 = 0.0f;
    for (int r = 0; r < 256; r++) {
        float v = X[(r0 + r) * C_ + c];
        s += v;
        s2 += v * v;
    }
    part[blockIdx.x * 768 + c] = s;
    part[blockIdx.x * 768 + 384 + c] = s2;
}

__global__ void bn_finalize(const float* __restrict__ part, float* __restrict__ stats) {
    int c = threadIdx.x;
    float s = 0.0f, s2 = 0.0f;
    for (int p = 0; p < 98; p++) {
        s += part[p * 768 + c];
        s2 += part[p * 768 + 384 + c];
    }
    const float inv = 1.0f / 25088.0f;
    float m = s * inv;
    float var = s2 * inv - m * m;
    stats[c] = m;
    stats[384 + c] = 1.0f / sqrtf(var + 1e-5f);
}

// ---------------- fused BN-apply + 4-step LIF (+ optional residual) ----------------
__global__ void bn_lif4(const float* __restrict__ lin, float* __restrict__ out,
                        const float* __restrict__ stats,
                        const float* __restrict__ gamma, const float* __restrict__ beta,
                        const float* __restrict__ lif_w, int widx,
                        const float* __restrict__ xadd) {
    long idx = (long)blockIdx.x * blockDim.x + threadIdx.x;
    if (idx >= (long)BNC_) return;
    int c = (int)(idx % C_);
    float mu = stats[c], rstd = stats[384 + c];
    float gg = gamma[c], bb = beta[c];
    float decay = 1.0f / (1.0f + expf(-lif_w[widx]));
    float v = 0.0f;
    float xs[4];
#pragma unroll
    for (int t = 0; t < 4; t++) xs[t] = lin[(long)t * BNC_ + idx];
#pragma unroll
    for (int t = 0; t < 4; t++) {
        long o = (long)t * BNC_ + idx;
        float xv = (xs[t] - mu) * rstd * gg + bb;
        v = v + (xv - v) * decay;
        float s = (v >= 1.0f) ? 1.0f : 0.0f;
        v *= (1.0f - s);
        if (xadd) out[o] = xadd[o] + s;
        else      out[o] = s;
    }
}

// ---------------- launch ----------------
extern "C" void kernel_launch(void* const* d_in, const int* in_sizes, int n_in,
                              void* d_out, int out_size) {
    const float* x      = (const float*)d_in[0];
    const float* q_w    = (const float*)d_in[1];
    const float* q_b    = (const float*)d_in[2];
    const float* k_w    = (const float*)d_in[3];
    const float* k_b    = (const float*)d_in[4];
    const float* v_w    = (const float*)d_in[5];
    const float* v_b    = (const float*)d_in[6];
    const float* ap_w   = (const float*)d_in[7];
    const float* ap_b   = (const float*)d_in[8];
    const float* fc1_w  = (const float*)d_in[9];
    const float* fc1_b  = (const float*)d_in[10];
    const float* rec_w  = (const float*)d_in[11];
    const float* rec_b  = (const float*)d_in[12];
    const float* fc2_w  = (const float*)d_in[13];
    const float* fc2_b  = (const float*)d_in[14];
    const float* bnl_g  = (const float*)d_in[15];
    const float* bnl_b  = (const float*)d_in[16];
    const float* watt_w = (const float*)d_in[17];
    const float* watt_b = (const float*)d_in[18];
    const float* wlsm_w = (const float*)d_in[19];
    const float* wlsm_b = (const float*)d_in[20];
    const float* fp_w   = (const float*)d_in[21];
    const float* fp_b   = (const float*)d_in[22];
    const float* bnf_g  = (const float*)d_in[23];
    const float* bnf_b  = (const float*)d_in[24];
    const float* lif_w  = (const float*)d_in[25];
    float* out = (float*)d_out;

    float *bq, *bk, *bv, *ab, *af, *curr, *syn, *mem, *spk, *l, *ga, *gl, *o, *part, *stats;
    float *apT, *watT, *wlsT, *fpT, *recT, *fc2T;
    cudaGetSymbolAddress((void**)&bq, g_bq);
    cudaGetSymbolAddress((void**)&bk, g_bk);
    cudaGetSymbolAddress((void**)&bv, g_bv);
    cudaGetSymbolAddress((void**)&ab, g_ab);
    cudaGetSymbolAddress((void**)&af, g_af);
    cudaGetSymbolAddress((void**)&curr, g_curr);
    cudaGetSymbolAddress((void**)&syn, g_syn);
    cudaGetSymbolAddress((void**)&mem, g_mem);
    cudaGetSymbolAddress((void**)&spk, g_spk);
    cudaGetSymbolAddress((void**)&l, g_l);
    cudaGetSymbolAddress((void**)&ga, g_ga);
    cudaGetSymbolAddress((void**)&gl, g_gl);
    cudaGetSymbolAddress((void**)&o, g_o);
    cudaGetSymbolAddress((void**)&part, g_part);
    cudaGetSymbolAddress((void**)&stats, g_stats);
    cudaGetSymbolAddress((void**)&apT, g_apT);
    cudaGetSymbolAddress((void**)&watT, g_watT);
    cudaGetSymbolAddress((void**)&wlsT, g_wlsT);
    cudaGetSymbolAddress((void**)&fpT, g_fpT);
    cudaGetSymbolAddress((void**)&recT, g_recT);
    cudaGetSymbolAddress((void**)&fc2T, g_fc2T);

    const dim3 gC(C_ / BN, TBN_ / BM);     // (3, 196)
    const dim3 gH(HID_ / BN, TBN_ / BM);   // (12, 196) fc1
    const dim3 gR(HID_ / BN, BN_ / BM);    // (12, 49)  rec dense
    const int nb75k = (NC_ + 255) / 256;
    const int nbHALF = (HALF_ + 255) / 256;
    const int nbBNC = (BNC_ + 255) / 256;
    const int nbMH  = (MH_ + 255) / 256;
    const dim3 tb32(32, 8);
    const dim3 gT384(C_ / 32, C_ / 32);
    const dim3 gT1536(HID_ / 32, HID_ / 32);
    const dim3 gTfc2(HID_ / 32, C_ / 32);

    // ---- two-stream fork/join: SSA branch on s2, LSM branch on default ----
    cudaStream_t s2;
    cudaStreamCreateWithFlags(&s2, cudaStreamNonBlocking);
    cudaEvent_t evFork, evJoin;
    cudaEventCreateWithFlags(&evFork, cudaEventDisableTiming);
    cudaEventCreateWithFlags(&evJoin, cudaEventDisableTiming);

    // ---- prep: weight transposes (default stream) ----
    transpose_k<<<gT384, tb32>>>(ap_w, apT, C_, C_);
    transpose_k<<<gT384, tb32>>>(watt_w, watT, C_, C_);
    transpose_k<<<gT384, tb32>>>(wlsm_w, wlsT, C_, C_);
    transpose_k<<<gT384, tb32>>>(fp_w, fpT, C_, C_);
    transpose_k<<<gT1536, tb32>>>(rec_w, recT, HID_, HID_);
    transpose_k<<<gTfc2, tb32>>>(fc2_w, fc2T, C_, HID_);

    cudaEventRecord(evFork, 0);
    cudaStreamWaitEvent(s2, evFork, 0);

    // --- SSA branch on s2 ---
    sgemm_nt<<<gC, 256, 0, s2>>>(x, q_w, q_b, bq, TBN_, C_, C_);
    sgemm_nt<<<gC, 256, 0, s2>>>(x, k_w, k_b, bk, TBN_, C_, C_);
    sgemm_nt<<<gC, 256, 0, s2>>>(x, v_w, v_b, bv, TBN_, C_, C_);
    lif_seq3<<<dim3(nbHALF, 3), 256, 0, s2>>>(bq, bk, bv, lif_w);
    attn_kernel<<<TB_ * H_, 256, 0, s2>>>(bq, bk, bv, ab);
    lif_seq<<<nbBNC, 256, 0, s2>>>(ab, T_, BNC_, BNC_, lif_w, 3);
    spmm_gather<2><<<TBN_, 256, 0, s2>>>(ab, apT, ap_b, af, C_, C_);
    lif_seq<<<nb75k, 256, 0, s2>>>(af, TB_, NC_, NC_, lif_w, 4);
    cudaEventRecord(evJoin, s2);

    // --- LSM branch on default stream ---
    sgemm_nt<<<gH, 256>>>(x, fc1_w, fc1_b, curr, TBN_, HID_, C_);
    lsm_step0<<<nbMH, 256>>>(curr, rec_b, syn, mem, spk);
    spmm_gather_lsm<<<BN_, 256>>>(spk, recT, rec_b,
                                  curr + (size_t)MH_, syn, mem,
                                  spk, spk + (size_t)MH_);
    spmm_gather_lsm<<<BN_, 256>>>(spk + (size_t)MH_, recT, rec_b,
                                  curr + 2 * (size_t)MH_, syn, mem,
                                  spk + (size_t)MH_, spk + 2 * (size_t)MH_);
    sgemm_nt_lsm<<<gR, 256>>>(spk + 2 * (size_t)MH_, rec_w, rec_b,
                              curr + 3 * (size_t)MH_, syn, mem,
                              spk + 2 * (size_t)MH_, spk + 3 * (size_t)MH_,
                              BN_, HID_);

    spmm_gather<2><<<BN_, 256>>>(spk, fc2T, fc2_b, l, C_, HID_);
    spmm_gather<2><<<BN_, 256>>>(spk + (size_t)MH_, fc2T, fc2_b,
                                 l + (size_t)BN_ * C_, C_, HID_);
    sgemm_nt<<<dim3(C_ / BN, (2 * BN_) / BM), 256>>>(spk + 2 * (size_t)MH_, fc2_w, fc2_b,
                                                     l + 2 * (size_t)BN_ * C_,
                                                     2 * BN_, C_, HID_);
    bn_partial<<<98, 384>>>(l, part);
    bn_finalize<<<1, 384>>>(part, stats);
    bn_lif4<<<nbBNC, 256>>>(l, l, stats, bnl_g, bnl_b, lif_w, 5, nullptr);

    // gl depends only on l -> launch before joining with SSA
    spmm_gather<2><<<TBN_, 256>>>(l, wlsT, wlsm_b, gl, C_, C_);

    // --- join: ARIG needs af (SSA) ---
    cudaStreamWaitEvent(0, evJoin, 0);
    spmm_gather<2><<<TBN_, 256>>>(af, watT, watt_b, ga, C_, C_);
    spmm_gather_fuse<2><<<TBN_, 256>>>(af, l, ga, gl, fpT, fp_b, o, C_, C_);
    bn_partial<<<98, 384>>>(o, part);
    bn_finalize<<<1, 384>>>(part, stats);
    bn_lif4<<<nbBNC, 256>>>(o, out, stats, bnf_g, bnf_b, lif_w, 6, x);

    cudaEventDestroy(evFork);
    cudaEventDestroy(evJoin);
    cudaStreamDestroy(s2);
}